// round 2
// baseline (speedup 1.0000x reference)
#include <cuda_runtime.h>
#include <math.h>

#define E_TOT 262144
#define NN    16384
#define H     256
#define NG    64
#define BVW   260        // padded row width for b_v-augmented (256 + head + tail + pad)
#define KEU   772        // 3H + 4

// ---------------- scratch (device globals; no allocation allowed) ----------------
__device__ float g_be[(size_t)E_TOT * H];      // edge states b_e       (256 MB)
__device__ float g_hidden[(size_t)E_TOT * H];  // eu MLP hidden         (256 MB)
__device__ float g_score[E_TOT];
__device__ float g_ex[E_TOT];
__device__ float g_m[NN];
__device__ float g_s[NN];
__device__ float g_bvaug[(size_t)NN * BVW];    // [b_v | is_head | is_tail | pad]
__device__ float g_gG[NG * 768];
__device__ float g_z[NG];

// ---------------- small elementwise kernels ----------------

__global__ void init_be_kernel(const float* __restrict__ ef, const float* __restrict__ gall) {
    int t = blockIdx.x * 256 + threadIdx.x;      // E*H threads
    int e = t >> 8, j = t & 255;
    g_be[t] = (j < 192) ? ef[(size_t)e * 192 + j] : gall[j - 192];
}

__global__ void init_iter_kernel() {
    int t = blockIdx.x * 256 + threadIdx.x;
    if (t < NN * BVW) g_bvaug[t] = 0.f;
    if (t < NN) { g_m[t] = 0.f; g_s[t] = 0.f; }  // scores are sigmoids > 0, so 0 is a valid -inf
}

__global__ void segmax_kernel(const int* __restrict__ recv) {
    int e = blockIdx.x * 256 + threadIdx.x;
    float sc = g_score[e];
    // positive floats compare correctly as ints
    atomicMax((int*)&g_m[recv[e]], __float_as_int(sc));
}

__global__ void exsum_kernel(const int* __restrict__ recv) {
    int e = blockIdx.x * 256 + threadIdx.x;
    int r = recv[e];
    float ex = expf(g_score[e] - g_m[r]);
    g_ex[e] = ex;
    atomicAdd(&g_s[r], ex);
}

__global__ void scatter_kernel(const int* __restrict__ recv) {
    int t = blockIdx.x * 256 + threadIdx.x;      // E*64 threads, 4 cols each
    int e = t >> 6, c = t & 63;
    int r = recv[e];
    float alpha = g_ex[e] / g_s[r];
    float4 b = *(const float4*)(g_be + (size_t)e * H + c * 4);
    float* dst = g_bvaug + (size_t)r * BVW + c * 4;
    atomicAdd(dst + 0, alpha * b.x);
    atomicAdd(dst + 1, alpha * b.y);
    atomicAdd(dst + 2, alpha * b.z);
    atomicAdd(dst + 3, alpha * b.w);
}

__global__ void finalize_kernel(const int* __restrict__ deg, const int* __restrict__ batch,
                                const int* __restrict__ heads, const int* __restrict__ tails) {
    int t = blockIdx.x * 256 + threadIdx.x;      // N*H threads
    int n = t >> 8, j = t & 255;
    float inv = 1.f / (1.f + (float)deg[n]);
    g_bvaug[(size_t)n * BVW + j] *= inv;
    if (j == 0) {
        int b = batch[n];
        g_bvaug[(size_t)n * BVW + 256] = (heads[b] == n) ? 1.f : 0.f;
        g_bvaug[(size_t)n * BVW + 257] = (tails[b] == n) ? 1.f : 0.f;
    }
}

// ---------------- GEMM kernels: 64x256 block tile, K-tile 32, 8x8 per thread ----------------
// Packed-f32x2 inner loop: accumulators pair adjacent n-columns in one 64-bit
// register pair; B pairs come straight from Bs (adjacent floats); the A value
// is stored PRE-DUPLICATED in As2 (As2[k][2r]=As2[k][2r+1]=A[r][k]) so the
// broadcast pack {a,a} is a plain LDS.128 — no per-iteration MOV packing.
// 32 FFMA2 per k-step instead of 64 FFMA.

#define GEMM_INNER_PK()                                                     \
    _Pragma("unroll")                                                       \
    for (int kk = 0; kk < 32; kk++) {                                       \
        unsigned long long a2[8], b2[4];                                    \
        *(ulonglong2*)&a2[0] = *(ulonglong2*)&As2[kk][ty * 16];             \
        *(ulonglong2*)&a2[2] = *(ulonglong2*)&As2[kk][ty * 16 + 4];         \
        *(ulonglong2*)&a2[4] = *(ulonglong2*)&As2[kk][ty * 16 + 8];         \
        *(ulonglong2*)&a2[6] = *(ulonglong2*)&As2[kk][ty * 16 + 12];        \
        *(ulonglong2*)&b2[0] = *(ulonglong2*)&Bs[kk][tx * 4];               \
        *(ulonglong2*)&b2[2] = *(ulonglong2*)&Bs[kk][128 + tx * 4];         \
        _Pragma("unroll")                                                   \
        for (int m = 0; m < 8; m++)                                         \
            _Pragma("unroll")                                               \
            for (int j = 0; j < 4; j++)                                     \
                asm("fma.rn.f32x2 %0, %1, %2, %0;"                          \
                    : "+l"(acc2[m][j]) : "l"(a2[m]), "l"(b2[j]));           \
    }

#define UNPACK_ACC()                                                        \
    float acc[8][8];                                                        \
    _Pragma("unroll")                                                       \
    for (int m = 0; m < 8; m++)                                             \
        _Pragma("unroll")                                                   \
        for (int j = 0; j < 4; j++) {                                       \
            acc[m][2 * j]     = __uint_as_float((unsigned)acc2[m][j]);      \
            acc[m][2 * j + 1] = __uint_as_float((unsigned)(acc2[m][j] >> 32)); \
        }

// score = sigmoid(relu(b_e @ W1 + b1) @ w2 + b2), fully fused
__global__ __launch_bounds__(256) void score_gemm(
    const float* __restrict__ W1, const float* __restrict__ b1,
    const float* __restrict__ w2, const float* __restrict__ b2)
{
    __shared__ float As2[32][136];    // duplicated A: [k][2r]=[k][2r+1]
    __shared__ float Bs[32][256];
    const int tid = threadIdx.x;
    const int tx = tid & 31, ty = tid >> 5;
    const int row0 = blockIdx.x * 64;
    unsigned long long acc2[8][4];
    #pragma unroll
    for (int m = 0; m < 8; m++)
        #pragma unroll
        for (int j = 0; j < 4; j++) acc2[m][j] = 0ull;

    for (int kt = 0; kt < H; kt += 32) {
        #pragma unroll
        for (int i = 0; i < 2; i++) {
            int idx = tid + i * 256;
            int r = idx >> 3, k4 = idx & 7;
            float4 a = *(const float4*)(g_be + (size_t)(row0 + r) * H + kt + k4 * 4);
            *(float2*)&As2[k4 * 4 + 0][2 * r] = make_float2(a.x, a.x);
            *(float2*)&As2[k4 * 4 + 1][2 * r] = make_float2(a.y, a.y);
            *(float2*)&As2[k4 * 4 + 2][2 * r] = make_float2(a.z, a.z);
            *(float2*)&As2[k4 * 4 + 3][2 * r] = make_float2(a.w, a.w);
        }
        #pragma unroll
        for (int i = 0; i < 8; i++) {
            int idx = tid + i * 256;
            int k = idx >> 6, n4 = idx & 63;
            *(float4*)&Bs[k][n4 * 4] = *(const float4*)(W1 + (size_t)(kt + k) * H + n4 * 4);
        }
        __syncthreads();
        GEMM_INNER_PK();
        __syncthreads();
    }

    UNPACK_ACC();
    float bb[8], ww[8];
    #pragma unroll
    for (int n = 0; n < 4; n++) {
        bb[n] = b1[tx * 4 + n];           ww[n] = w2[tx * 4 + n];
        bb[n + 4] = b1[128 + tx * 4 + n]; ww[n + 4] = w2[128 + tx * 4 + n];
    }
    float part[8];
    #pragma unroll
    for (int m = 0; m < 8; m++) {
        float s = 0.f;
        #pragma unroll
        for (int n = 0; n < 8; n++) {
            float h = fmaxf(acc[m][n] + bb[n], 0.f);
            s = fmaf(h, ww[n], s);
        }
        part[m] = s;
    }
    #pragma unroll
    for (int off = 16; off > 0; off >>= 1)
        #pragma unroll
        for (int m = 0; m < 8; m++) part[m] += __shfl_xor_sync(0xffffffffu, part[m], off);
    if (tx == 0) {
        float bias2 = b2[0];
        #pragma unroll
        for (int m = 0; m < 8; m++) {
            float x = part[m] + bias2;
            g_score[row0 + ty * 8 + m] = 1.f / (1.f + expf(-x));
        }
    }
}

// hidden = relu([r_v[src] | r_v[recv] | b_e] @ W1 + b1), gather fused into A-tile load
__global__ __launch_bounds__(256) void eu1_gemm(
    const int* __restrict__ src, const int* __restrict__ recv,
    const float* __restrict__ W1, const float* __restrict__ b1)
{
    __shared__ float As2[32][136];
    __shared__ float Bs[32][256];
    __shared__ int s_src[64], s_recv[64];
    const int tid = threadIdx.x;
    const int tx = tid & 31, ty = tid >> 5;
    const int row0 = blockIdx.x * 64;
    if (tid < 64) { s_src[tid] = src[row0 + tid]; s_recv[tid] = recv[row0 + tid]; }
    __syncthreads();
    unsigned long long acc2[8][4];
    #pragma unroll
    for (int m = 0; m < 8; m++)
        #pragma unroll
        for (int j = 0; j < 4; j++) acc2[m][j] = 0ull;

    for (int kt = 0; kt < KEU; kt += 32) {
        #pragma unroll
        for (int i = 0; i < 8; i++) {
            int idx = tid + i * 256;
            int r = idx >> 5, kk = idx & 31;
            int k = kt + kk;
            float v = 0.f;
            if (k < KEU) {
                if (k < 258)      v = g_bvaug[(size_t)s_src[r] * BVW + k];
                else if (k < 516) v = g_bvaug[(size_t)s_recv[r] * BVW + (k - 258)];
                else              v = g_be[(size_t)(row0 + r) * H + (k - 516)];
            }
            *(float2*)&As2[kk][2 * r] = make_float2(v, v);
        }
        #pragma unroll
        for (int i = 0; i < 8; i++) {
            int idx = tid + i * 256;
            int k = idx >> 6, n4 = idx & 63;
            float4 bv = make_float4(0.f, 0.f, 0.f, 0.f);
            if (kt + k < KEU) bv = *(const float4*)(W1 + (size_t)(kt + k) * H + n4 * 4);
            *(float4*)&Bs[k][n4 * 4] = bv;
        }
        __syncthreads();
        GEMM_INNER_PK();
        __syncthreads();
    }

    UNPACK_ACC();
    float bb[8];
    #pragma unroll
    for (int n = 0; n < 4; n++) { bb[n] = b1[tx * 4 + n]; bb[n + 4] = b1[128 + tx * 4 + n]; }
    #pragma unroll
    for (int m = 0; m < 8; m++) {
        float4 h0 = make_float4(fmaxf(acc[m][0] + bb[0], 0.f), fmaxf(acc[m][1] + bb[1], 0.f),
                                fmaxf(acc[m][2] + bb[2], 0.f), fmaxf(acc[m][3] + bb[3], 0.f));
        float4 h1 = make_float4(fmaxf(acc[m][4] + bb[4], 0.f), fmaxf(acc[m][5] + bb[5], 0.f),
                                fmaxf(acc[m][6] + bb[6], 0.f), fmaxf(acc[m][7] + bb[7], 0.f));
        float* dst = g_hidden + (size_t)(row0 + ty * 8 + m) * H;
        *(float4*)(dst + tx * 4) = h0;
        *(float4*)(dst + 128 + tx * 4) = h1;
    }
}

// b_e = hidden @ W2 + b2; last iter: w_e = sigmoid(b_e @ ew_w + ew_b) fused, b_e store skipped
__global__ __launch_bounds__(256) void eu2_gemm(
    const float* __restrict__ W2, const float* __restrict__ b2,
    float* __restrict__ we_out, const float* __restrict__ eww, const float* __restrict__ ewb)
{
    __shared__ float As2[32][136];
    __shared__ float Bs[32][256];
    const int tid = threadIdx.x;
    const int tx = tid & 31, ty = tid >> 5;
    const int row0 = blockIdx.x * 64;
    unsigned long long acc2[8][4];
    #pragma unroll
    for (int m = 0; m < 8; m++)
        #pragma unroll
        for (int j = 0; j < 4; j++) acc2[m][j] = 0ull;

    for (int kt = 0; kt < H; kt += 32) {
        #pragma unroll
        for (int i = 0; i < 2; i++) {
            int idx = tid + i * 256;
            int r = idx >> 3, k4 = idx & 7;
            float4 a = *(const float4*)(g_hidden + (size_t)(row0 + r) * H + kt + k4 * 4);
            *(float2*)&As2[k4 * 4 + 0][2 * r] = make_float2(a.x, a.x);
            *(float2*)&As2[k4 * 4 + 1][2 * r] = make_float2(a.y, a.y);
            *(float2*)&As2[k4 * 4 + 2][2 * r] = make_float2(a.z, a.z);
            *(float2*)&As2[k4 * 4 + 3][2 * r] = make_float2(a.w, a.w);
        }
        #pragma unroll
        for (int i = 0; i < 8; i++) {
            int idx = tid + i * 256;
            int k = idx >> 6, n4 = idx & 63;
            *(float4*)&Bs[k][n4 * 4] = *(const float4*)(W2 + (size_t)(kt + k) * H + n4 * 4);
        }
        __syncthreads();
        GEMM_INNER_PK();
        __syncthreads();
    }

    UNPACK_ACC();
    float bb[8];
    #pragma unroll
    for (int n = 0; n < 4; n++) { bb[n] = b2[tx * 4 + n]; bb[n + 4] = b2[128 + tx * 4 + n]; }

    if (we_out == nullptr) {
        #pragma unroll
        for (int m = 0; m < 8; m++) {
            float4 h0 = make_float4(acc[m][0] + bb[0], acc[m][1] + bb[1],
                                    acc[m][2] + bb[2], acc[m][3] + bb[3]);
            float4 h1 = make_float4(acc[m][4] + bb[4], acc[m][5] + bb[5],
                                    acc[m][6] + bb[6], acc[m][7] + bb[7]);
            float* dst = g_be + (size_t)(row0 + ty * 8 + m) * H;
            *(float4*)(dst + tx * 4) = h0;
            *(float4*)(dst + 128 + tx * 4) = h1;
        }
    } else {
        float ww[8];
        #pragma unroll
        for (int n = 0; n < 4; n++) { ww[n] = eww[tx * 4 + n]; ww[n + 4] = eww[128 + tx * 4 + n]; }
        float part[8];
        #pragma unroll
        for (int m = 0; m < 8; m++) {
            float s = 0.f;
            #pragma unroll
            for (int n = 0; n < 8; n++) s = fmaf(acc[m][n] + bb[n], ww[n], s);
            part[m] = s;
        }
        #pragma unroll
        for (int off = 16; off > 0; off >>= 1)
            #pragma unroll
            for (int m = 0; m < 8; m++) part[m] += __shfl_xor_sync(0xffffffffu, part[m], off);
        if (tx == 0) {
            float bias = ewb[0];
            #pragma unroll
            for (int m = 0; m < 8; m++) {
                float x = part[m] + bias;
                we_out[row0 + ty * 8 + m] = 1.f / (1.f + expf(-x));
            }
        }
    }
}

// ---------------- graph readout ----------------

__global__ void gmax_kernel(const int* __restrict__ heads, const int* __restrict__ tails) {
    int g = blockIdx.x, j = threadIdx.x;         // 64 blocks x 256 threads
    float mx = -3.4e38f;
    int base = g * 256;
    for (int n = 0; n < 256; n++)
        mx = fmaxf(mx, g_bvaug[(size_t)(base + n) * BVW + j]);
    g_gG[g * 768 + j]       = mx;
    g_gG[g * 768 + 256 + j] = g_bvaug[(size_t)heads[g] * BVW + j];
    g_gG[g * 768 + 512 + j] = g_bvaug[(size_t)tails[g] * BVW + j];
}

__global__ void gmlp_kernel(const float* __restrict__ W1, const float* __restrict__ b1,
                            const float* __restrict__ w2, const float* __restrict__ b2) {
    __shared__ float row[768];
    __shared__ float red[256];
    int g = blockIdx.x, tid = threadIdx.x;
    for (int i = tid; i < 768; i += 256) row[i] = g_gG[g * 768 + i];
    __syncthreads();
    float h = b1[tid];
    for (int k = 0; k < 768; k++) h = fmaf(row[k], W1[(size_t)k * 256 + tid], h);
    h = fmaxf(h, 0.f);
    red[tid] = h * w2[tid];
    __syncthreads();
    for (int s = 128; s > 0; s >>= 1) {
        if (tid < s) red[tid] += red[tid + s];
        __syncthreads();
    }
    if (tid == 0) g_z[g] = red[0] + b2[0];
}

__global__ void gout_kernel(float* __restrict__ out) {
    __shared__ float zs[NG];
    int tid = threadIdx.x;                       // 768 threads
    if (tid < NG) zs[tid] = g_z[tid];
    __syncthreads();
    float m = -3.4e38f;
    for (int g = 0; g < NG; g++) m = fmaxf(m, zs[g]);
    float denom = 0.f;
    for (int g = 0; g < NG; g++) denom += expf(zs[g] - m);
    float acc = 0.f;
    for (int g = 0; g < NG; g++) acc += (expf(zs[g] - m) / denom) * g_gG[g * 768 + tid];
    out[tid] = acc;
}

// ---------------- launch ----------------

extern "C" void kernel_launch(void* const* d_in, const int* in_sizes, int n_in,
                              void* d_out, int out_size) {
    const float* ef     = (const float*)d_in[0];
    const float* gall   = (const float*)d_in[1];
    const float* ea_w1  = (const float*)d_in[2];
    const float* ea_b1  = (const float*)d_in[3];
    const float* ea_w2  = (const float*)d_in[4];
    const float* ea_b2  = (const float*)d_in[5];
    const float* eu_w1  = (const float*)d_in[6];
    const float* eu_b1  = (const float*)d_in[7];
    const float* eu_w2  = (const float*)d_in[8];
    const float* eu_b2  = (const float*)d_in[9];
    const float* gw_w1  = (const float*)d_in[10];
    const float* gw_b1  = (const float*)d_in[11];
    const float* gw_w2  = (const float*)d_in[12];
    const float* gw_b2  = (const float*)d_in[13];
    const float* ew_w   = (const float*)d_in[14];
    const float* ew_b   = (const float*)d_in[15];
    const int*   eidx   = (const int*)d_in[16];
    const int*   deg    = (const int*)d_in[17];
    const int*   batch  = (const int*)d_in[18];
    const int*   heads  = (const int*)d_in[19];
    const int*   tails  = (const int*)d_in[20];
    const int* src  = eidx;
    const int* recv = eidx + E_TOT;
    float* out = (float*)d_out;

    init_be_kernel<<<E_TOT, 256>>>(ef, gall);

    for (int it = 0; it < 3; it++) {
        init_iter_kernel<<<(NN * BVW + 255) / 256, 256>>>();
        score_gemm<<<E_TOT / 64, 256>>>(ea_w1, ea_b1, ea_w2, ea_b2);
        segmax_kernel<<<E_TOT / 256, 256>>>(recv);
        exsum_kernel<<<E_TOT / 256, 256>>>(recv);
        scatter_kernel<<<(E_TOT * 64) / 256, 256>>>(recv);
        finalize_kernel<<<NN, 256>>>(deg, batch, heads, tails);
        eu1_gemm<<<E_TOT / 64, 256>>>(src, recv, eu_w1, eu_b1);
        eu2_gemm<<<E_TOT / 64, 256>>>(eu_w2, eu_b2,
                                      (it == 2) ? out : (float*)nullptr, ew_w, ew_b);
    }

    gmax_kernel<<<NG, 256>>>(heads, tails);
    gmlp_kernel<<<NG, 256>>>(gw_w1, gw_b1, gw_w2, gw_b2);
    gout_kernel<<<1, 768>>>(out + E_TOT);
}

// round 5
// speedup vs baseline: 1.3726x; 1.3726x over previous
#include <cuda_runtime.h>
#include <cuda_bf16.h>
#include <cstdint>
#include <math.h>

#define E_TOT 262144
#define NN    16384
#define H     256
#define NG    64
#define BVW   260        // padded row width for b_v-augmented (256 + head + tail + pad)
#define KEU_PAD 800      // 772 padded to multiple of 32

// ---------------- scratch (device globals; no allocation allowed) ----------------
__device__ float g_be[(size_t)E_TOT * H];
__device__ float g_hidden[(size_t)E_TOT * H];
__device__ float g_score[E_TOT];
__device__ float g_ex[E_TOT];
__device__ float g_m[NN];
__device__ float g_s[NN];
__device__ float g_bvaug[(size_t)NN * BVW];
__device__ float g_gG[NG * 768];
__device__ float g_z[NG];

// pre-split bf16 weights, K-major B[n][k] = W[k][n], zero-padded K
__device__ __nv_bfloat16 g_bhi_ea[256 * 256],      g_blo_ea[256 * 256];
__device__ __nv_bfloat16 g_bhi_eu1[256 * KEU_PAD], g_blo_eu1[256 * KEU_PAD];
__device__ __nv_bfloat16 g_bhi_eu2[256 * 256],     g_blo_eu2[256 * 256];

// ---------------- weight pre-split kernels ----------------

__global__ void prep_ea(const float* __restrict__ W) {
    int idx = blockIdx.x * 256 + threadIdx.x;           // 256*256
    int n = idx >> 8, k = idx & 255;
    float x = W[(size_t)k * 256 + n];
    __nv_bfloat16 h = __float2bfloat16(x);
    g_bhi_ea[(size_t)n * 256 + k] = h;
    g_blo_ea[(size_t)n * 256 + k] = __float2bfloat16(x - __bfloat162float(h));
}
__global__ void prep_eu1(const float* __restrict__ W) {
    int idx = blockIdx.x * 256 + threadIdx.x;           // 256*800
    int n = idx / KEU_PAD, k = idx % KEU_PAD;
    float x = (k < 772) ? W[(size_t)k * 256 + n] : 0.f;
    __nv_bfloat16 h = __float2bfloat16(x);
    g_bhi_eu1[(size_t)n * KEU_PAD + k] = h;
    g_blo_eu1[(size_t)n * KEU_PAD + k] = __float2bfloat16(x - __bfloat162float(h));
}
__global__ void prep_eu2(const float* __restrict__ W) {
    int idx = blockIdx.x * 256 + threadIdx.x;
    int n = idx >> 8, k = idx & 255;
    float x = W[(size_t)k * 256 + n];
    __nv_bfloat16 h = __float2bfloat16(x);
    g_bhi_eu2[(size_t)n * 256 + k] = h;
    g_blo_eu2[(size_t)n * 256 + k] = __float2bfloat16(x - __bfloat162float(h));
}

// ---------------- small elementwise kernels ----------------

__global__ void init_be_kernel(const float* __restrict__ ef, const float* __restrict__ gall) {
    int t = blockIdx.x * 256 + threadIdx.x;
    int e = t >> 8, j = t & 255;
    g_be[t] = (j < 192) ? ef[(size_t)e * 192 + j] : gall[j - 192];
}

__global__ void init_iter_kernel() {
    int t = blockIdx.x * 256 + threadIdx.x;
    if (t < NN * BVW) g_bvaug[t] = 0.f;
    if (t < NN) { g_m[t] = 0.f; g_s[t] = 0.f; }
}

__global__ void segmax_kernel(const int* __restrict__ recv) {
    int e = blockIdx.x * 256 + threadIdx.x;
    atomicMax((int*)&g_m[recv[e]], __float_as_int(g_score[e]));
}

__global__ void exsum_kernel(const int* __restrict__ recv) {
    int e = blockIdx.x * 256 + threadIdx.x;
    int r = recv[e];
    float ex = expf(g_score[e] - g_m[r]);
    g_ex[e] = ex;
    atomicAdd(&g_s[r], ex);
}

__global__ void scatter_kernel(const int* __restrict__ recv) {
    int t = blockIdx.x * 256 + threadIdx.x;
    int e = t >> 6, c = t & 63;
    int r = recv[e];
    float alpha = g_ex[e] / g_s[r];
    float4 b = *(const float4*)(g_be + (size_t)e * H + c * 4);
    float* dst = g_bvaug + (size_t)r * BVW + c * 4;
    atomicAdd(dst + 0, alpha * b.x);
    atomicAdd(dst + 1, alpha * b.y);
    atomicAdd(dst + 2, alpha * b.z);
    atomicAdd(dst + 3, alpha * b.w);
}

__global__ void finalize_kernel(const int* __restrict__ deg, const int* __restrict__ batch,
                                const int* __restrict__ heads, const int* __restrict__ tails) {
    int t = blockIdx.x * 256 + threadIdx.x;
    int n = t >> 8, j = t & 255;
    float inv = 1.f / (1.f + (float)deg[n]);
    g_bvaug[(size_t)n * BVW + j] *= inv;
    if (j == 0) {
        int b = batch[n];
        g_bvaug[(size_t)n * BVW + 256] = (heads[b] == n) ? 1.f : 0.f;
        g_bvaug[(size_t)n * BVW + 257] = (tails[b] == n) ? 1.f : 0.f;
    }
}

// ---------------- mma.sync bf16 GEMM: CTA 64x256, warp 32x64, split-2 ----------------
// MODE 0: score  = sigmoid(relu(be@W+b1)@wv+wb)        A=g_be,      out=g_score
// MODE 1: hidden = relu([bv[src]|bv[recv]|be]@W+b1)    A=gathered,  out=g_hidden (K=772->800)
// MODE 2: be     = hidden@W+b1                          A=g_hidden,  out=g_be
// MODE 3: w_e    = sigmoid((hidden@W+b1)@wv+wb)         A=g_hidden,  out=outp

#define ASTRIDE 40   // bf16 elements per A smem row (pad for conflict-free frags)
#define BSTRIDE 40
// smem byte offsets
#define OFF_AHI 0
#define OFF_ALO 5120
#define OFF_BHI 10240
#define OFF_BLO 30720
#define OFF_SB1 51200
#define OFF_SWV 52224
#define OFF_RSUM 53248
#define OFF_SRC 53504
#define OFF_RECV 53760
#define SMEM_BYTES 54016

#define MMA_BF16(d, a, b0, b1)                                              \
    asm volatile("mma.sync.aligned.m16n8k16.row.col.f32.bf16.bf16.f32 "     \
        "{%0,%1,%2,%3}, {%4,%5,%6,%7}, {%8,%9}, {%0,%1,%2,%3};"             \
        : "+f"((d)[0]), "+f"((d)[1]), "+f"((d)[2]), "+f"((d)[3])            \
        : "r"((a)[0]), "r"((a)[1]), "r"((a)[2]), "r"((a)[3]),               \
          "r"(b0), "r"(b1))

__device__ __forceinline__ uint32_t pack_hi(float x, float y,
                                            uint32_t& lo_out) {
    __nv_bfloat16 hx = __float2bfloat16(x), hy = __float2bfloat16(y);
    __nv_bfloat16 lx = __float2bfloat16(x - __bfloat162float(hx));
    __nv_bfloat16 ly = __float2bfloat16(y - __bfloat162float(hy));
    lo_out = (uint32_t)__bfloat16_as_ushort(lx) | ((uint32_t)__bfloat16_as_ushort(ly) << 16);
    return (uint32_t)__bfloat16_as_ushort(hx) | ((uint32_t)__bfloat16_as_ushort(hy) << 16);
}

template<int MODE>
__global__ __launch_bounds__(256) void mma_gemm(
    const float* __restrict__ b1v, const float* __restrict__ wv, const float* __restrict__ wb,
    const int* __restrict__ srcp, const int* __restrict__ recvp, float* __restrict__ outp)
{
    constexpr int KPAD = (MODE == 1) ? KEU_PAD : 256;
    extern __shared__ char smem[];
    __nv_bfloat16* Ah = (__nv_bfloat16*)(smem + OFF_AHI);
    __nv_bfloat16* Al = (__nv_bfloat16*)(smem + OFF_ALO);
    __nv_bfloat16* Bh = (__nv_bfloat16*)(smem + OFF_BHI);
    __nv_bfloat16* Bl = (__nv_bfloat16*)(smem + OFF_BLO);
    float* sb1   = (float*)(smem + OFF_SB1);
    float* swv   = (float*)(smem + OFF_SWV);
    float* rsum  = (float*)(smem + OFF_RSUM);
    int*   s_src = (int*)(smem + OFF_SRC);
    int*   s_rcv = (int*)(smem + OFF_RECV);

    const int tid = threadIdx.x, lane = tid & 31, wid = tid >> 5;
    const int row0 = blockIdx.x * 64;
    const int mbase = (wid >> 2) * 32, nbase = (wid & 3) * 64;

    sb1[tid] = b1v[tid];
    if (MODE == 0 || MODE == 3) swv[tid] = wv[tid];
    if (MODE == 1 && tid < 64) { s_src[tid] = srcp[row0 + tid]; s_rcv[tid] = recvp[row0 + tid]; }
    if (tid < 64) rsum[tid] = 0.f;
    __syncthreads();

    const __nv_bfloat16* Bhi_g = (MODE == 0) ? g_bhi_ea : (MODE == 1) ? g_bhi_eu1 : g_bhi_eu2;
    const __nv_bfloat16* Blo_g = (MODE == 0) ? g_blo_ea : (MODE == 1) ? g_blo_eu1 : g_blo_eu2;

    float acc[2][8][4];
    #pragma unroll
    for (int mf = 0; mf < 2; mf++)
        #pragma unroll
        for (int nf = 0; nf < 8; nf++)
            #pragma unroll
            for (int q = 0; q < 4; q++) acc[mf][nf][q] = 0.f;

    const int arow = tid >> 2, ac0 = (tid & 3) * 8;

    for (int kt = 0; kt < KPAD; kt += 32) {
        // ---- stage A (fp32 -> hi/lo bf16), 8 elements per thread ----
        {
            float x[8];
            if (MODE == 0) {
                *(float4*)&x[0] = *(const float4*)(g_be + (size_t)(row0 + arow) * H + kt + ac0);
                *(float4*)&x[4] = *(const float4*)(g_be + (size_t)(row0 + arow) * H + kt + ac0 + 4);
            } else if (MODE >= 2) {
                *(float4*)&x[0] = *(const float4*)(g_hidden + (size_t)(row0 + arow) * H + kt + ac0);
                *(float4*)&x[4] = *(const float4*)(g_hidden + (size_t)(row0 + arow) * H + kt + ac0 + 4);
            } else {
                #pragma unroll
                for (int q = 0; q < 8; q++) {
                    int kk = kt + ac0 + q;
                    float v = 0.f;
                    if (kk < 258)      v = g_bvaug[(size_t)s_src[arow] * BVW + kk];
                    else if (kk < 516) v = g_bvaug[(size_t)s_rcv[arow] * BVW + (kk - 258)];
                    else if (kk < 772) v = g_be[(size_t)(row0 + arow) * H + (kk - 516)];
                    x[q] = v;
                }
            }
            uint4 uh, ul;
            uh.x = pack_hi(x[0], x[1], ul.x);
            uh.y = pack_hi(x[2], x[3], ul.y);
            uh.z = pack_hi(x[4], x[5], ul.z);
            uh.w = pack_hi(x[6], x[7], ul.w);
            *(uint4*)&Ah[arow * ASTRIDE + ac0] = uh;
            *(uint4*)&Al[arow * ASTRIDE + ac0] = ul;
        }
        // ---- stage B (pre-split bf16), 32 k per thread-row ----
        {
            const __nv_bfloat16* bh = Bhi_g + (size_t)tid * KPAD + kt;
            const __nv_bfloat16* bl = Blo_g + (size_t)tid * KPAD + kt;
            #pragma unroll
            for (int j = 0; j < 4; j++) {
                *(uint4*)&Bh[tid * BSTRIDE + j * 8] = *(const uint4*)(bh + j * 8);
                *(uint4*)&Bl[tid * BSTRIDE + j * 8] = *(const uint4*)(bl + j * 8);
            }
        }
        __syncthreads();
        // ---- 2 x k16 MMA steps ----
        #pragma unroll
        for (int ks = 0; ks < 2; ks++) {
            const int k0 = ks * 16 + (lane & 3) * 2;
            uint32_t ahi[2][4], alo[2][4];
            #pragma unroll
            for (int mf = 0; mf < 2; mf++) {
                int r = mbase + mf * 16 + (lane >> 2);
                ahi[mf][0] = *(uint32_t*)&Ah[r * ASTRIDE + k0];
                ahi[mf][1] = *(uint32_t*)&Ah[(r + 8) * ASTRIDE + k0];
                ahi[mf][2] = *(uint32_t*)&Ah[r * ASTRIDE + k0 + 8];
                ahi[mf][3] = *(uint32_t*)&Ah[(r + 8) * ASTRIDE + k0 + 8];
                alo[mf][0] = *(uint32_t*)&Al[r * ASTRIDE + k0];
                alo[mf][1] = *(uint32_t*)&Al[(r + 8) * ASTRIDE + k0];
                alo[mf][2] = *(uint32_t*)&Al[r * ASTRIDE + k0 + 8];
                alo[mf][3] = *(uint32_t*)&Al[(r + 8) * ASTRIDE + k0 + 8];
            }
            #pragma unroll
            for (int nf = 0; nf < 8; nf++) {
                int n = nbase + nf * 8 + (lane >> 2);
                uint32_t bh0 = *(uint32_t*)&Bh[n * BSTRIDE + k0];
                uint32_t bh1 = *(uint32_t*)&Bh[n * BSTRIDE + k0 + 8];
                uint32_t bl0 = *(uint32_t*)&Bl[n * BSTRIDE + k0];
                uint32_t bl1 = *(uint32_t*)&Bl[n * BSTRIDE + k0 + 8];
                #pragma unroll
                for (int mf = 0; mf < 2; mf++) {
                    MMA_BF16(acc[mf][nf], ahi[mf], bh0, bh1);
                    MMA_BF16(acc[mf][nf], alo[mf], bh0, bh1);
                    MMA_BF16(acc[mf][nf], ahi[mf], bl0, bl1);
                }
            }
        }
        __syncthreads();
    }

    // ---- epilogue ----
    if (MODE == 0 || MODE == 3) {
        float part[2][2] = {{0.f, 0.f}, {0.f, 0.f}};
        #pragma unroll
        for (int mf = 0; mf < 2; mf++)
            #pragma unroll
            for (int nf = 0; nf < 8; nf++) {
                int c0 = nbase + nf * 8 + (lane & 3) * 2;
                float w0 = swv[c0], w1 = swv[c0 + 1];
                float bb0 = sb1[c0], bb1 = sb1[c0 + 1];
                float v0 = acc[mf][nf][0] + bb0, v1 = acc[mf][nf][1] + bb1;
                float v2 = acc[mf][nf][2] + bb0, v3 = acc[mf][nf][3] + bb1;
                if (MODE == 0) {
                    v0 = fmaxf(v0, 0.f); v1 = fmaxf(v1, 0.f);
                    v2 = fmaxf(v2, 0.f); v3 = fmaxf(v3, 0.f);
                }
                part[mf][0] = fmaf(v0, w0, fmaf(v1, w1, part[mf][0]));
                part[mf][1] = fmaf(v2, w0, fmaf(v3, w1, part[mf][1]));
            }
        #pragma unroll
        for (int off = 1; off <= 2; off <<= 1)
            #pragma unroll
            for (int mf = 0; mf < 2; mf++) {
                part[mf][0] += __shfl_xor_sync(0xffffffffu, part[mf][0], off);
                part[mf][1] += __shfl_xor_sync(0xffffffffu, part[mf][1], off);
            }
        if ((lane & 3) == 0) {
            #pragma unroll
            for (int mf = 0; mf < 2; mf++) {
                atomicAdd(&rsum[mbase + mf * 16 + (lane >> 2)],     part[mf][0]);
                atomicAdd(&rsum[mbase + mf * 16 + (lane >> 2) + 8], part[mf][1]);
            }
        }
        __syncthreads();
        if (tid < 64) {
            float xx = rsum[tid] + wb[0];
            float sg = 1.f / (1.f + expf(-xx));
            if (MODE == 0) g_score[row0 + tid] = sg;
            else           outp[row0 + tid] = sg;
        }
    } else {
        float* dstg = (MODE == 1) ? g_hidden : g_be;
        #pragma unroll
        for (int mf = 0; mf < 2; mf++)
            #pragma unroll
            for (int nf = 0; nf < 8; nf++) {
                int r = mbase + mf * 16 + (lane >> 2);
                int c0 = nbase + nf * 8 + (lane & 3) * 2;
                float bb0 = sb1[c0], bb1 = sb1[c0 + 1];
                float2 v0 = make_float2(acc[mf][nf][0] + bb0, acc[mf][nf][1] + bb1);
                float2 v1 = make_float2(acc[mf][nf][2] + bb0, acc[mf][nf][3] + bb1);
                if (MODE == 1) {
                    v0.x = fmaxf(v0.x, 0.f); v0.y = fmaxf(v0.y, 0.f);
                    v1.x = fmaxf(v1.x, 0.f); v1.y = fmaxf(v1.y, 0.f);
                }
                *(float2*)(dstg + (size_t)(row0 + r) * H + c0) = v0;
                *(float2*)(dstg + (size_t)(row0 + r + 8) * H + c0) = v1;
            }
    }
}

// ---------------- graph readout ----------------

__global__ void gmax_kernel(const int* __restrict__ heads, const int* __restrict__ tails) {
    int g = blockIdx.x, j = threadIdx.x;
    float mx = -3.4e38f;
    int base = g * 256;
    for (int n = 0; n < 256; n++)
        mx = fmaxf(mx, g_bvaug[(size_t)(base + n) * BVW + j]);
    g_gG[g * 768 + j]       = mx;
    g_gG[g * 768 + 256 + j] = g_bvaug[(size_t)heads[g] * BVW + j];
    g_gG[g * 768 + 512 + j] = g_bvaug[(size_t)tails[g] * BVW + j];
}

__global__ void gmlp_kernel(const float* __restrict__ W1, const float* __restrict__ b1,
                            const float* __restrict__ w2, const float* __restrict__ b2) {
    __shared__ float row[768];
    __shared__ float red[256];
    int g = blockIdx.x, tid = threadIdx.x;
    for (int i = tid; i < 768; i += 256) row[i] = g_gG[g * 768 + i];
    __syncthreads();
    float h = b1[tid];
    for (int k = 0; k < 768; k++) h = fmaf(row[k], W1[(size_t)k * 256 + tid], h);
    h = fmaxf(h, 0.f);
    red[tid] = h * w2[tid];
    __syncthreads();
    for (int s = 128; s > 0; s >>= 1) {
        if (tid < s) red[tid] += red[tid + s];
        __syncthreads();
    }
    if (tid == 0) g_z[g] = red[0] + b2[0];
}

__global__ void gout_kernel(float* __restrict__ out) {
    __shared__ float zs[NG];
    int tid = threadIdx.x;
    if (tid < NG) zs[tid] = g_z[tid];
    __syncthreads();
    float m = -3.4e38f;
    for (int g = 0; g < NG; g++) m = fmaxf(m, zs[g]);
    float denom = 0.f;
    for (int g = 0; g < NG; g++) denom += expf(zs[g] - m);
    float acc = 0.f;
    for (int g = 0; g < NG; g++) acc += (expf(zs[g] - m) / denom) * g_gG[g * 768 + tid];
    out[tid] = acc;
}

// ---------------- launch ----------------

extern "C" void kernel_launch(void* const* d_in, const int* in_sizes, int n_in,
                              void* d_out, int out_size) {
    const float* ef     = (const float*)d_in[0];
    const float* gall   = (const float*)d_in[1];
    const float* ea_w1  = (const float*)d_in[2];
    const float* ea_b1  = (const float*)d_in[3];
    const float* ea_w2  = (const float*)d_in[4];
    const float* ea_b2  = (const float*)d_in[5];
    const float* eu_w1  = (const float*)d_in[6];
    const float* eu_b1  = (const float*)d_in[7];
    const float* eu_w2  = (const float*)d_in[8];
    const float* eu_b2  = (const float*)d_in[9];
    const float* gw_w1  = (const float*)d_in[10];
    const float* gw_b1  = (const float*)d_in[11];
    const float* gw_w2  = (const float*)d_in[12];
    const float* gw_b2  = (const float*)d_in[13];
    const float* ew_w   = (const float*)d_in[14];
    const float* ew_b   = (const float*)d_in[15];
    const int*   eidx   = (const int*)d_in[16];
    const int*   deg    = (const int*)d_in[17];
    const int*   batch  = (const int*)d_in[18];
    const int*   heads  = (const int*)d_in[19];
    const int*   tails  = (const int*)d_in[20];
    const int* src  = eidx;
    const int* recv = eidx + E_TOT;
    float* out = (float*)d_out;

    cudaFuncSetAttribute(mma_gemm<0>, cudaFuncAttributeMaxDynamicSharedMemorySize, SMEM_BYTES);
    cudaFuncSetAttribute(mma_gemm<1>, cudaFuncAttributeMaxDynamicSharedMemorySize, SMEM_BYTES);
    cudaFuncSetAttribute(mma_gemm<2>, cudaFuncAttributeMaxDynamicSharedMemorySize, SMEM_BYTES);
    cudaFuncSetAttribute(mma_gemm<3>, cudaFuncAttributeMaxDynamicSharedMemorySize, SMEM_BYTES);

    prep_ea<<<256, 256>>>(ea_w1);
    prep_eu1<<<KEU_PAD, 256>>>(eu_w1);
    prep_eu2<<<256, 256>>>(eu_w2);
    init_be_kernel<<<E_TOT, 256>>>(ef, gall);

    for (int it = 0; it < 3; it++) {
        init_iter_kernel<<<(NN * BVW + 255) / 256, 256>>>();
        mma_gemm<0><<<E_TOT / 64, 256, SMEM_BYTES>>>(ea_b1, ea_w2, ea_b2, nullptr, nullptr, nullptr);
        segmax_kernel<<<E_TOT / 256, 256>>>(recv);
        exsum_kernel<<<E_TOT / 256, 256>>>(recv);
        scatter_kernel<<<(E_TOT * 64) / 256, 256>>>(recv);
        finalize_kernel<<<NN, 256>>>(deg, batch, heads, tails);
        mma_gemm<1><<<E_TOT / 64, 256, SMEM_BYTES>>>(eu_b1, nullptr, nullptr, src, recv, nullptr);
        if (it < 2)
            mma_gemm<2><<<E_TOT / 64, 256, SMEM_BYTES>>>(eu_b2, nullptr, nullptr, nullptr, nullptr, nullptr);
        else
            mma_gemm<3><<<E_TOT / 64, 256, SMEM_BYTES>>>(eu_b2, ew_w, ew_b, nullptr, nullptr, out);
    }

    gmax_kernel<<<NG, 256>>>(heads, tails);
    gmlp_kernel<<<NG, 256>>>(gw_w1, gw_b1, gw_w2, gw_b2);
    gout_kernel<<<1, 768>>>(out + E_TOT);
}

// round 6
// speedup vs baseline: 2.5155x; 1.8326x over previous
#include <cuda_runtime.h>
#include <cuda_bf16.h>
#include <cstdint>
#include <math.h>

#define E_TOT 262144
#define NN    16384
#define H     256
#define NG    64

// ---------------- scratch (device globals; no allocation allowed) ----------------
__device__ float g_be[(size_t)E_TOT * H];       // b_e^0 (iter-0 edge state)
__device__ float g_hidden[(size_t)E_TOT * H];   // hidden_t
__device__ float g_score[E_TOT];
__device__ float g_ex[E_TOT];
__device__ float g_m[NN];
__device__ float g_s[NN];
__device__ float g_bv[(size_t)NN * H];          // node state b_v
__device__ float g_agg[(size_t)NN * H];         // segsum(alpha*hidden)
__device__ float g_U[(size_t)NN * H];
__device__ float g_V[(size_t)NN * H];
__device__ float g_gG[NG * 768];
__device__ float g_z[NG];

// composed fp32 weights / vectors
__device__ float g_Wsc[H * H];    // W2 @ ea_w1
__device__ float g_Wth[H * H];    // W2 @ W1c
__device__ float g_cbsc[H];       // b2@ea_w1 + ea_b1
__device__ float g_cbth[H];       // b2@W1c + eu_b1
__device__ float g_wcomp[H];      // W2 @ ew_w
__device__ float g_cconst[1];     // b2@ew_w + ew_b
__device__ float g_inv[NN], g_rs[NN], g_ish[NN], g_ist[NN];

// bf16 hi/lo splits, K-major B[n][k]
__device__ __nv_bfloat16 g_hi_sc0[H*H], g_lo_sc0[H*H];   // ea_w1
__device__ __nv_bfloat16 g_hi_sc[H*H],  g_lo_sc[H*H];    // Wsc
__device__ __nv_bfloat16 g_hi_th0[H*H], g_lo_th0[H*H];   // W1c
__device__ __nv_bfloat16 g_hi_th[H*H],  g_lo_th[H*H];    // Wth
__device__ __nv_bfloat16 g_hi_u[H*H],   g_lo_u[H*H];     // W1a (rows 0..255)
__device__ __nv_bfloat16 g_hi_v[H*H],   g_lo_v[H*H];     // W1b (rows 258..513)
__device__ __nv_bfloat16 g_hi_w2[H*H],  g_lo_w2[H*H];    // W2

// ---------------- prep kernels ----------------

// C[k][n] = sum_j L[k*256+j] * R[j*256+n]
__global__ void comp_mat(const float* __restrict__ L, const float* __restrict__ R,
                         float* __restrict__ C) {
    __shared__ float lrow[H];
    int k = blockIdx.x, n = threadIdx.x;
    lrow[n] = L[k * H + n];
    __syncthreads();
    float acc = 0.f;
    for (int j = 0; j < H; j++) acc = fmaf(lrow[j], R[j * H + n], acc);
    C[k * H + n] = acc;
}

__global__ void comp_vec(const float* __restrict__ eu_w2, const float* __restrict__ eu_b2,
                         const float* __restrict__ ea_w1, const float* __restrict__ ea_b1,
                         const float* __restrict__ w1c, const float* __restrict__ eu_b1,
                         const float* __restrict__ ew_w, const float* __restrict__ ew_b) {
    int n = threadIdx.x;
    float a = 0.f, b = 0.f, w = 0.f;
    for (int k = 0; k < H; k++) {
        a = fmaf(eu_b2[k], ea_w1[k * H + n], a);
        b = fmaf(eu_b2[k], w1c[k * H + n], b);
        w = fmaf(eu_w2[n * H + k], ew_w[k], w);
    }
    g_cbsc[n] = a + ea_b1[n];
    g_cbth[n] = b + eu_b1[n];
    g_wcomp[n] = w;
    if (n == 0) {
        float c = 0.f;
        for (int j = 0; j < H; j++) c = fmaf(eu_b2[j], ew_w[j], c);
        g_cconst[0] = c + ew_b[0];
    }
}

// split W ([k][n] row-major, stride 256) into K-major bf16 hi/lo
__global__ void split_w(const float* __restrict__ W, __nv_bfloat16* __restrict__ hi,
                        __nv_bfloat16* __restrict__ lo) {
    int idx = blockIdx.x * 256 + threadIdx.x;
    int n = idx >> 8, k = idx & 255;
    float x = W[(size_t)k * H + n];
    __nv_bfloat16 h = __float2bfloat16(x);
    hi[(size_t)n * H + k] = h;
    lo[(size_t)n * H + k] = __float2bfloat16(x - __bfloat162float(h));
}

__global__ void deg_kernel(const int* __restrict__ deg, const int* __restrict__ batch,
                           const int* __restrict__ heads, const int* __restrict__ tails) {
    int n = blockIdx.x * 256 + threadIdx.x;
    int d = deg[n];
    float inv = 1.f / (1.f + (float)d);
    g_inv[n] = inv;
    g_rs[n] = (d > 0) ? inv : 0.f;
    int b = batch[n];
    g_ish[n] = (heads[b] == n) ? 1.f : 0.f;
    g_ist[n] = (tails[b] == n) ? 1.f : 0.f;
}

__global__ void init_be_kernel(const float* __restrict__ ef, const float* __restrict__ gall) {
    int t = blockIdx.x * 256 + threadIdx.x;      // E*64 threads, float4 each
    int e = t >> 6, j4 = t & 63;
    float4 v;
    if (j4 < 48) v = *(const float4*)(ef + (size_t)e * 192 + j4 * 4);
    else         v = *(const float4*)(gall + (j4 - 48) * 4);
    *(float4*)(g_be + (size_t)e * H + j4 * 4) = v;
}

// ---------------- per-iteration small kernels ----------------

__global__ void init_iter_kernel(float* __restrict__ dst) {   // zero dst (N*H) + m/s
    int t = blockIdx.x * 256 + threadIdx.x;
    if (t < NN * H) dst[t] = 0.f;
    if (t < NN) { g_m[t] = 0.f; g_s[t] = 0.f; }
}

__global__ void segmax_kernel(const int* __restrict__ recv) {
    int e = blockIdx.x * 256 + threadIdx.x;
    atomicMax((int*)&g_m[recv[e]], __float_as_int(g_score[e]));   // scores > 0
}

__global__ void exsum_kernel(const int* __restrict__ recv) {
    int e = blockIdx.x * 256 + threadIdx.x;
    int r = recv[e];
    float ex = expf(g_score[e] - g_m[r]);
    g_ex[e] = ex;
    atomicAdd(&g_s[r], ex);
}

__global__ void scatter_kernel(const float* __restrict__ X, float* __restrict__ dst,
                               const int* __restrict__ recv) {
    int t = blockIdx.x * 256 + threadIdx.x;      // E*64 threads, 4 cols each
    int e = t >> 6, c = t & 63;
    int r = recv[e];
    float alpha = g_ex[e] / g_s[r];
    float4 b = *(const float4*)(X + (size_t)e * H + c * 4);
    float* d = dst + (size_t)r * H + c * 4;
    atomicAdd(d + 0, alpha * b.x);
    atomicAdd(d + 1, alpha * b.y);
    atomicAdd(d + 2, alpha * b.z);
    atomicAdd(d + 3, alpha * b.w);
}

__global__ void finalize0_kernel() {             // t=0: b_v = agg / (1+deg)
    int t = blockIdx.x * 256 + threadIdx.x;      // N*H
    g_bv[t] *= g_inv[t >> 8];
}

// ---------------- mma.sync bf16 GEMM: CTA 64x256, warp 32x64, split-2 (3 terms) ----------------
// MODE 0 SCORE : out_score = sigmoid(relu(A@B + bias) @ wv + wb)
// MODE 1 HIDDEN: out = relu(A@B + bias + U[src] + V[recv])
// MODE 2 NODEUV: out = A@B + ish[r]*fH + ist[r]*fT
// MODE 3 NODEBV: out = (A*inv[r])@B + rs[r]*bias

#define ASTRIDE 40
#define BSTRIDE 40
#define OFF_AHI 0
#define OFF_ALO 5120
#define OFF_BHI 10240
#define OFF_BLO 30720
#define OFF_SB1 51200
#define OFF_SWV 52224
#define OFF_RSUM 53248
#define OFF_SRC 53504
#define OFF_RECV 53760
#define OFF_R1 54016
#define OFF_R2 54272
#define SMEM_BYTES 54528

#define MMA_BF16(d, a, b0, b1)                                              \
    asm volatile("mma.sync.aligned.m16n8k16.row.col.f32.bf16.bf16.f32 "     \
        "{%0,%1,%2,%3}, {%4,%5,%6,%7}, {%8,%9}, {%0,%1,%2,%3};"             \
        : "+f"((d)[0]), "+f"((d)[1]), "+f"((d)[2]), "+f"((d)[3])            \
        : "r"((a)[0]), "r"((a)[1]), "r"((a)[2]), "r"((a)[3]),               \
          "r"(b0), "r"(b1))

__device__ __forceinline__ uint32_t pack_hi(float x, float y, uint32_t& lo_out) {
    __nv_bfloat16 hx = __float2bfloat16(x), hy = __float2bfloat16(y);
    __nv_bfloat16 lx = __float2bfloat16(x - __bfloat162float(hx));
    __nv_bfloat16 ly = __float2bfloat16(y - __bfloat162float(hy));
    lo_out = (uint32_t)__bfloat16_as_ushort(lx) | ((uint32_t)__bfloat16_as_ushort(ly) << 16);
    return (uint32_t)__bfloat16_as_ushort(hx) | ((uint32_t)__bfloat16_as_ushort(hy) << 16);
}

template<int MODE>
__global__ __launch_bounds__(256) void mma_gemm(
    const float* __restrict__ A,
    const __nv_bfloat16* __restrict__ Bhig, const __nv_bfloat16* __restrict__ Blog,
    const float* __restrict__ bias,
    const float* __restrict__ aux1, const float* __restrict__ aux2,
    const float* __restrict__ auxs,
    const int* __restrict__ srcp, const int* __restrict__ recvp,
    const float* __restrict__ rowv1, const float* __restrict__ rowv2,
    float* __restrict__ outp)
{
    extern __shared__ char smem[];
    __nv_bfloat16* Ah = (__nv_bfloat16*)(smem + OFF_AHI);
    __nv_bfloat16* Al = (__nv_bfloat16*)(smem + OFF_ALO);
    __nv_bfloat16* Bh = (__nv_bfloat16*)(smem + OFF_BHI);
    __nv_bfloat16* Bl = (__nv_bfloat16*)(smem + OFF_BLO);
    float* sb1   = (float*)(smem + OFF_SB1);
    float* swv   = (float*)(smem + OFF_SWV);
    float* rsum  = (float*)(smem + OFF_RSUM);
    int*   s_src = (int*)(smem + OFF_SRC);
    int*   s_rcv = (int*)(smem + OFF_RECV);
    float* s_r1  = (float*)(smem + OFF_R1);
    float* s_r2  = (float*)(smem + OFF_R2);

    const int tid = threadIdx.x, lane = tid & 31, wid = tid >> 5;
    const int row0 = blockIdx.x * 64;
    const int mbase = (wid >> 2) * 32, nbase = (wid & 3) * 64;

    if (MODE != 2) sb1[tid] = bias[tid];
    if (MODE == 0) { swv[tid] = aux1[tid]; if (tid < 64) rsum[tid] = 0.f; }
    if (MODE == 1 && tid < 64) { s_src[tid] = srcp[row0 + tid]; s_rcv[tid] = recvp[row0 + tid]; }
    if ((MODE == 2 || MODE == 3) && tid < 64) {
        s_r1[tid] = rowv1[row0 + tid];
        s_r2[tid] = rowv2[row0 + tid];
    }
    __syncthreads();

    float acc[2][8][4];
    #pragma unroll
    for (int mf = 0; mf < 2; mf++)
        #pragma unroll
        for (int nf = 0; nf < 8; nf++)
            #pragma unroll
            for (int q = 0; q < 4; q++) acc[mf][nf][q] = 0.f;

    const int arow = tid >> 2, ac0 = (tid & 3) * 8;

    for (int kt = 0; kt < H; kt += 32) {
        // ---- stage A (fp32 -> hi/lo bf16) ----
        {
            float x[8];
            *(float4*)&x[0] = *(const float4*)(A + (size_t)(row0 + arow) * H + kt + ac0);
            *(float4*)&x[4] = *(const float4*)(A + (size_t)(row0 + arow) * H + kt + ac0 + 4);
            if (MODE == 3) {
                float sc = s_r1[arow];
                #pragma unroll
                for (int q = 0; q < 8; q++) x[q] *= sc;
            }
            uint4 uh, ul;
            uh.x = pack_hi(x[0], x[1], ul.x);
            uh.y = pack_hi(x[2], x[3], ul.y);
            uh.z = pack_hi(x[4], x[5], ul.z);
            uh.w = pack_hi(x[6], x[7], ul.w);
            *(uint4*)&Ah[arow * ASTRIDE + ac0] = uh;
            *(uint4*)&Al[arow * ASTRIDE + ac0] = ul;
        }
        // ---- stage B (pre-split bf16) ----
        {
            const __nv_bfloat16* bh = Bhig + (size_t)tid * H + kt;
            const __nv_bfloat16* bl = Blog + (size_t)tid * H + kt;
            #pragma unroll
            for (int j = 0; j < 4; j++) {
                *(uint4*)&Bh[tid * BSTRIDE + j * 8] = *(const uint4*)(bh + j * 8);
                *(uint4*)&Bl[tid * BSTRIDE + j * 8] = *(const uint4*)(bl + j * 8);
            }
        }
        __syncthreads();
        #pragma unroll
        for (int ks = 0; ks < 2; ks++) {
            const int k0 = ks * 16 + (lane & 3) * 2;
            uint32_t ahi[2][4], alo[2][4];
            #pragma unroll
            for (int mf = 0; mf < 2; mf++) {
                int r = mbase + mf * 16 + (lane >> 2);
                ahi[mf][0] = *(uint32_t*)&Ah[r * ASTRIDE + k0];
                ahi[mf][1] = *(uint32_t*)&Ah[(r + 8) * ASTRIDE + k0];
                ahi[mf][2] = *(uint32_t*)&Ah[r * ASTRIDE + k0 + 8];
                ahi[mf][3] = *(uint32_t*)&Ah[(r + 8) * ASTRIDE + k0 + 8];
                alo[mf][0] = *(uint32_t*)&Al[r * ASTRIDE + k0];
                alo[mf][1] = *(uint32_t*)&Al[(r + 8) * ASTRIDE + k0];
                alo[mf][2] = *(uint32_t*)&Al[r * ASTRIDE + k0 + 8];
                alo[mf][3] = *(uint32_t*)&Al[(r + 8) * ASTRIDE + k0 + 8];
            }
            #pragma unroll
            for (int nf = 0; nf < 8; nf++) {
                int n = nbase + nf * 8 + (lane >> 2);
                uint32_t bh0 = *(uint32_t*)&Bh[n * BSTRIDE + k0];
                uint32_t bh1 = *(uint32_t*)&Bh[n * BSTRIDE + k0 + 8];
                uint32_t bl0 = *(uint32_t*)&Bl[n * BSTRIDE + k0];
                uint32_t bl1 = *(uint32_t*)&Bl[n * BSTRIDE + k0 + 8];
                #pragma unroll
                for (int mf = 0; mf < 2; mf++) {
                    MMA_BF16(acc[mf][nf], ahi[mf], bh0, bh1);
                    MMA_BF16(acc[mf][nf], alo[mf], bh0, bh1);
                    MMA_BF16(acc[mf][nf], ahi[mf], bl0, bl1);
                }
            }
        }
        __syncthreads();
    }

    // ---- epilogues ----
    if (MODE == 0) {
        float part[2][2] = {{0.f, 0.f}, {0.f, 0.f}};
        #pragma unroll
        for (int mf = 0; mf < 2; mf++)
            #pragma unroll
            for (int nf = 0; nf < 8; nf++) {
                int c0 = nbase + nf * 8 + (lane & 3) * 2;
                float w0 = swv[c0], w1 = swv[c0 + 1];
                float bb0 = sb1[c0], bb1 = sb1[c0 + 1];
                float v0 = fmaxf(acc[mf][nf][0] + bb0, 0.f);
                float v1 = fmaxf(acc[mf][nf][1] + bb1, 0.f);
                float v2 = fmaxf(acc[mf][nf][2] + bb0, 0.f);
                float v3 = fmaxf(acc[mf][nf][3] + bb1, 0.f);
                part[mf][0] = fmaf(v0, w0, fmaf(v1, w1, part[mf][0]));
                part[mf][1] = fmaf(v2, w0, fmaf(v3, w1, part[mf][1]));
            }
        #pragma unroll
        for (int off = 1; off <= 2; off <<= 1)
            #pragma unroll
            for (int mf = 0; mf < 2; mf++) {
                part[mf][0] += __shfl_xor_sync(0xffffffffu, part[mf][0], off);
                part[mf][1] += __shfl_xor_sync(0xffffffffu, part[mf][1], off);
            }
        if ((lane & 3) == 0) {
            #pragma unroll
            for (int mf = 0; mf < 2; mf++) {
                atomicAdd(&rsum[mbase + mf * 16 + (lane >> 2)],     part[mf][0]);
                atomicAdd(&rsum[mbase + mf * 16 + (lane >> 2) + 8], part[mf][1]);
            }
        }
        __syncthreads();
        if (tid < 64)
            outp[row0 + tid] = 1.f / (1.f + expf(-(rsum[tid] + auxs[0])));
    } else {
        #pragma unroll
        for (int mf = 0; mf < 2; mf++)
            #pragma unroll
            for (int nf = 0; nf < 8; nf++) {
                int rA = mbase + mf * 16 + (lane >> 2);
                int rB = rA + 8;
                int c0 = nbase + nf * 8 + (lane & 3) * 2;
                float2 v0 = make_float2(acc[mf][nf][0], acc[mf][nf][1]);
                float2 v1 = make_float2(acc[mf][nf][2], acc[mf][nf][3]);
                if (MODE == 1) {
                    float bb0 = sb1[c0], bb1 = sb1[c0 + 1];
                    float2 ua = *(const float2*)(aux1 + (size_t)s_src[rA] * H + c0);
                    float2 va = *(const float2*)(aux2 + (size_t)s_rcv[rA] * H + c0);
                    float2 ub = *(const float2*)(aux1 + (size_t)s_src[rB] * H + c0);
                    float2 vb = *(const float2*)(aux2 + (size_t)s_rcv[rB] * H + c0);
                    v0.x = fmaxf(v0.x + bb0 + ua.x + va.x, 0.f);
                    v0.y = fmaxf(v0.y + bb1 + ua.y + va.y, 0.f);
                    v1.x = fmaxf(v1.x + bb0 + ub.x + vb.x, 0.f);
                    v1.y = fmaxf(v1.y + bb1 + ub.y + vb.y, 0.f);
                } else if (MODE == 2) {
                    float fh0 = __ldg(aux1 + c0), fh1 = __ldg(aux1 + c0 + 1);
                    float ft0 = __ldg(aux2 + c0), ft1 = __ldg(aux2 + c0 + 1);
                    v0.x += s_r1[rA] * fh0 + s_r2[rA] * ft0;
                    v0.y += s_r1[rA] * fh1 + s_r2[rA] * ft1;
                    v1.x += s_r1[rB] * fh0 + s_r2[rB] * ft0;
                    v1.y += s_r1[rB] * fh1 + s_r2[rB] * ft1;
                } else {  // MODE 3
                    float bb0 = sb1[c0], bb1 = sb1[c0 + 1];
                    v0.x += s_r2[rA] * bb0; v0.y += s_r2[rA] * bb1;
                    v1.x += s_r2[rB] * bb0; v1.y += s_r2[rB] * bb1;
                }
                *(float2*)(outp + (size_t)(row0 + rA) * H + c0) = v0;
                *(float2*)(outp + (size_t)(row0 + rB) * H + c0) = v1;
            }
    }
}

// ---------------- w_e matvec: out[e] = sigmoid(hidden[e]@wcomp + cconst) ----------------

__global__ void we_kernel(float* __restrict__ out) {
    __shared__ float wc[H];
    int tid = threadIdx.x, lane = tid & 31, wid = tid >> 5;
    wc[tid] = g_wcomp[tid];
    __syncthreads();
    int e = blockIdx.x * 8 + wid;
    const float* hrow = g_hidden + (size_t)e * H + lane * 8;
    float4 x0 = *(const float4*)hrow;
    float4 x1 = *(const float4*)(hrow + 4);
    const float* w = wc + lane * 8;
    float s = x0.x * w[0] + x0.y * w[1] + x0.z * w[2] + x0.w * w[3]
            + x1.x * w[4] + x1.y * w[5] + x1.z * w[6] + x1.w * w[7];
    #pragma unroll
    for (int off = 16; off > 0; off >>= 1) s += __shfl_xor_sync(0xffffffffu, s, off);
    if (lane == 0) out[e] = 1.f / (1.f + expf(-(s + g_cconst[0])));
}

// ---------------- graph readout ----------------

__global__ void gmax_kernel(const int* __restrict__ heads, const int* __restrict__ tails) {
    int g = blockIdx.x, j = threadIdx.x;
    float mx = -3.4e38f;
    int base = g * 256;
    for (int n = 0; n < 256; n++)
        mx = fmaxf(mx, g_bv[(size_t)(base + n) * H + j]);
    g_gG[g * 768 + j]       = mx;
    g_gG[g * 768 + 256 + j] = g_bv[(size_t)heads[g] * H + j];
    g_gG[g * 768 + 512 + j] = g_bv[(size_t)tails[g] * H + j];
}

__global__ void gmlp_kernel(const float* __restrict__ W1, const float* __restrict__ b1,
                            const float* __restrict__ w2, const float* __restrict__ b2) {
    __shared__ float row[768];
    __shared__ float red[256];
    int g = blockIdx.x, tid = threadIdx.x;
    for (int i = tid; i < 768; i += 256) row[i] = g_gG[g * 768 + i];
    __syncthreads();
    float h = b1[tid];
    for (int k = 0; k < 768; k++) h = fmaf(row[k], W1[(size_t)k * 256 + tid], h);
    h = fmaxf(h, 0.f);
    red[tid] = h * w2[tid];
    __syncthreads();
    for (int s = 128; s > 0; s >>= 1) {
        if (tid < s) red[tid] += red[tid + s];
        __syncthreads();
    }
    if (tid == 0) g_z[g] = red[0] + b2[0];
}

__global__ void gout_kernel(float* __restrict__ out) {
    __shared__ float zs[NG];
    int tid = threadIdx.x;
    if (tid < NG) zs[tid] = g_z[tid];
    __syncthreads();
    float m = -3.4e38f;
    for (int g = 0; g < NG; g++) m = fmaxf(m, zs[g]);
    float denom = 0.f;
    for (int g = 0; g < NG; g++) denom += expf(zs[g] - m);
    float acc = 0.f;
    for (int g = 0; g < NG; g++) acc += (expf(zs[g] - m) / denom) * g_gG[g * 768 + tid];
    out[tid] = acc;
}

// ---------------- launch ----------------

static float* dev_ptr(const void* sym) { void* p = nullptr; cudaGetSymbolAddress(&p, sym); return (float*)p; }

extern "C" void kernel_launch(void* const* d_in, const int* in_sizes, int n_in,
                              void* d_out, int out_size) {
    const float* ef     = (const float*)d_in[0];
    const float* gall   = (const float*)d_in[1];
    const float* ea_w1  = (const float*)d_in[2];
    const float* ea_b1  = (const float*)d_in[3];
    const float* ea_w2  = (const float*)d_in[4];
    const float* ea_b2  = (const float*)d_in[5];
    const float* eu_w1  = (const float*)d_in[6];
    const float* eu_b1  = (const float*)d_in[7];
    const float* eu_w2  = (const float*)d_in[8];
    const float* eu_b2  = (const float*)d_in[9];
    const float* gw_w1  = (const float*)d_in[10];
    const float* gw_b1  = (const float*)d_in[11];
    const float* gw_w2  = (const float*)d_in[12];
    const float* gw_b2  = (const float*)d_in[13];
    const float* ew_w   = (const float*)d_in[14];
    const float* ew_b   = (const float*)d_in[15];
    const int*   eidx   = (const int*)d_in[16];
    const int*   deg    = (const int*)d_in[17];
    const int*   batch  = (const int*)d_in[18];
    const int*   heads  = (const int*)d_in[19];
    const int*   tails  = (const int*)d_in[20];
    const int* src  = eidx;
    const int* recv = eidx + E_TOT;
    float* out = (float*)d_out;
    const float* w1c = eu_w1 + 516 * H;   // rows 516..771
    const float* w1a = eu_w1;             // rows 0..255 (+ flag rows 256,257)
    const float* w1b = eu_w1 + 258 * H;   // rows 258..513 (+ flag rows 514,515)

    cudaFuncSetAttribute(mma_gemm<0>, cudaFuncAttributeMaxDynamicSharedMemorySize, SMEM_BYTES);
    cudaFuncSetAttribute(mma_gemm<1>, cudaFuncAttributeMaxDynamicSharedMemorySize, SMEM_BYTES);
    cudaFuncSetAttribute(mma_gemm<2>, cudaFuncAttributeMaxDynamicSharedMemorySize, SMEM_BYTES);
    cudaFuncSetAttribute(mma_gemm<3>, cudaFuncAttributeMaxDynamicSharedMemorySize, SMEM_BYTES);

    // device-symbol addresses (host side, capture-safe)
    float *p_Wsc = dev_ptr(g_Wsc), *p_Wth = dev_ptr(g_Wth);
    float *p_cbsc = dev_ptr(g_cbsc), *p_cbth = dev_ptr(g_cbth);
    float *p_be = dev_ptr(g_be), *p_hidden = dev_ptr(g_hidden);
    float *p_bv = dev_ptr(g_bv), *p_agg = dev_ptr(g_agg);
    float *p_U = dev_ptr(g_U), *p_V = dev_ptr(g_V);
    float *p_score = dev_ptr(g_score);
    float *p_inv = dev_ptr(g_inv), *p_rs = dev_ptr(g_rs);
    float *p_ish = dev_ptr(g_ish), *p_ist = dev_ptr(g_ist);
    __nv_bfloat16 *h_sc0 = (__nv_bfloat16*)dev_ptr(g_hi_sc0), *l_sc0 = (__nv_bfloat16*)dev_ptr(g_lo_sc0);
    __nv_bfloat16 *h_sc  = (__nv_bfloat16*)dev_ptr(g_hi_sc),  *l_sc  = (__nv_bfloat16*)dev_ptr(g_lo_sc);
    __nv_bfloat16 *h_th0 = (__nv_bfloat16*)dev_ptr(g_hi_th0), *l_th0 = (__nv_bfloat16*)dev_ptr(g_lo_th0);
    __nv_bfloat16 *h_th  = (__nv_bfloat16*)dev_ptr(g_hi_th),  *l_th  = (__nv_bfloat16*)dev_ptr(g_lo_th);
    __nv_bfloat16 *h_u   = (__nv_bfloat16*)dev_ptr(g_hi_u),   *l_u   = (__nv_bfloat16*)dev_ptr(g_lo_u);
    __nv_bfloat16 *h_v   = (__nv_bfloat16*)dev_ptr(g_hi_v),   *l_v   = (__nv_bfloat16*)dev_ptr(g_lo_v);
    __nv_bfloat16 *h_w2  = (__nv_bfloat16*)dev_ptr(g_hi_w2),  *l_w2  = (__nv_bfloat16*)dev_ptr(g_lo_w2);

    // ---- prep ----
    deg_kernel<<<NN / 256, 256>>>(deg, batch, heads, tails);
    comp_mat<<<256, 256>>>(eu_w2, ea_w1, p_Wsc);
    comp_mat<<<256, 256>>>(eu_w2, w1c, p_Wth);
    comp_vec<<<1, 256>>>(eu_w2, eu_b2, ea_w1, ea_b1, w1c, eu_b1, ew_w, ew_b);
    split_w<<<256, 256>>>(ea_w1, h_sc0, l_sc0);
    split_w<<<256, 256>>>(p_Wsc, h_sc, l_sc);
    split_w<<<256, 256>>>(w1c, h_th0, l_th0);
    split_w<<<256, 256>>>(p_Wth, h_th, l_th);
    split_w<<<256, 256>>>(w1a, h_u, l_u);
    split_w<<<256, 256>>>(w1b, h_v, l_v);
    split_w<<<256, 256>>>(eu_w2, h_w2, l_w2);
    init_be_kernel<<<E_TOT / 4, 256>>>(ef, gall);

    for (int it = 0; it < 3; it++) {
        const float* Acur = (it == 0) ? p_be : p_hidden;
        float* aggdst = (it == 0) ? p_bv : p_agg;

        init_iter_kernel<<<(NN * H + 255) / 256, 256>>>(aggdst);
        // score
        mma_gemm<0><<<E_TOT / 64, 256, SMEM_BYTES>>>(
            Acur, (it == 0) ? h_sc0 : h_sc, (it == 0) ? l_sc0 : l_sc,
            (it == 0) ? ea_b1 : p_cbsc, ea_w2, nullptr, ea_b2,
            nullptr, nullptr, nullptr, nullptr, p_score);
        // softmax-aggregate
        segmax_kernel<<<E_TOT / 256, 256>>>(recv);
        exsum_kernel<<<E_TOT / 256, 256>>>(recv);
        scatter_kernel<<<(E_TOT * 64) / 256, 256>>>(Acur, aggdst, recv);
        if (it == 0)
            finalize0_kernel<<<(NN * H) / 256, 256>>>();
        else
            mma_gemm<3><<<NN / 64, 256, SMEM_BYTES>>>(
                p_agg, h_w2, l_w2, eu_b2, nullptr, nullptr, nullptr,
                nullptr, nullptr, p_inv, p_rs, p_bv);
        // U, V node GEMMs
        mma_gemm<2><<<NN / 64, 256, SMEM_BYTES>>>(
            p_bv, h_u, l_u, nullptr, eu_w1 + 256 * H, eu_w1 + 257 * H, nullptr,
            nullptr, nullptr, p_ish, p_ist, p_U);
        mma_gemm<2><<<NN / 64, 256, SMEM_BYTES>>>(
            p_bv, h_v, l_v, nullptr, eu_w1 + 514 * H, eu_w1 + 515 * H, nullptr,
            nullptr, nullptr, p_ish, p_ist, p_V);
        // hidden
        mma_gemm<1><<<E_TOT / 64, 256, SMEM_BYTES>>>(
            Acur, (it == 0) ? h_th0 : h_th, (it == 0) ? l_th0 : l_th,
            (it == 0) ? eu_b1 : p_cbth, p_U, p_V, nullptr,
            src, recv, nullptr, nullptr, p_hidden);
    }

    we_kernel<<<E_TOT / 8, 256>>>(out);
    gmax_kernel<<<NG, 256>>>(heads, tails);
    gmlp_kernel<<<NG, 256>>>(gw_w1, gw_b1, gw_w2, gw_b2);
    gout_kernel<<<1, 768>>>(out + E_TOT);
}

// round 7
// speedup vs baseline: 6.1552x; 2.4469x over previous
#include <cuda_runtime.h>
#include <cuda_fp16.h>
#include <cstdint>
#include <math.h>

#define E_TOT 262144
#define NN    16384
#define H     256
#define NG    64

// ---------------- scratch (device globals; no allocation allowed) ----------------
__device__ float g_be[(size_t)E_TOT * H];       // b_e^0 (iter-0 edge state)
__device__ float g_hidden[(size_t)E_TOT * H];   // hidden_t
__device__ float g_score[E_TOT];
__device__ float g_ex[E_TOT];
__device__ float g_m[NN];
__device__ float g_s[NN];
__device__ float g_bv[(size_t)NN * H];          // node state b_v
__device__ float g_agg[(size_t)NN * H];         // segsum(alpha*hidden)
__device__ float g_U[(size_t)NN * H];
__device__ float g_V[(size_t)NN * H];
__device__ float g_gG[NG * 768];
__device__ float g_z[NG];

// composed fp32 weights / vectors
__device__ float g_Wsc[H * H];    // W2 @ ea_w1
__device__ float g_Wth[H * H];    // W2 @ W1c
__device__ float g_cbsc[H];       // b2@ea_w1 + ea_b1
__device__ float g_cbth[H];       // b2@W1c + eu_b1
__device__ float g_wcomp[H];      // W2 @ ew_w
__device__ float g_cconst[1];     // b2@ew_w + ew_b
__device__ float g_inv[NN], g_rs[NN], g_ish[NN], g_ist[NN];

// fp16 weights, K-major B[n][k]
__device__ __half g_h_sc0[H*H];   // ea_w1
__device__ __half g_h_sc[H*H];    // Wsc
__device__ __half g_h_th0[H*H];   // W1c
__device__ __half g_h_th[H*H];    // Wth
__device__ __half g_h_u[H*H];     // W1a
__device__ __half g_h_v[H*H];     // W1b
__device__ __half g_h_w2[H*H];    // W2

// ---------------- prep kernels ----------------

// C[k][n] = sum_j L[k*256+j] * R[j*256+n]
__global__ void comp_mat(const float* __restrict__ L, const float* __restrict__ R,
                         float* __restrict__ C) {
    __shared__ float lrow[H];
    int k = blockIdx.x, n = threadIdx.x;
    lrow[n] = L[k * H + n];
    __syncthreads();
    float acc = 0.f;
    for (int j = 0; j < H; j++) acc = fmaf(lrow[j], R[j * H + n], acc);
    C[k * H + n] = acc;
}

__global__ void comp_vec(const float* __restrict__ eu_w2, const float* __restrict__ eu_b2,
                         const float* __restrict__ ea_w1, const float* __restrict__ ea_b1,
                         const float* __restrict__ w1c, const float* __restrict__ eu_b1,
                         const float* __restrict__ ew_w, const float* __restrict__ ew_b) {
    __shared__ float ra[H], rb[H], rw[H], rc[H];
    int n = blockIdx.x, k = threadIdx.x;
    float e2 = eu_b2[k];
    ra[k] = e2 * ea_w1[k * H + n];
    rb[k] = e2 * w1c[k * H + n];
    rw[k] = eu_w2[n * H + k] * ew_w[k];
    rc[k] = e2 * ew_w[k];
    __syncthreads();
    for (int s = 128; s > 0; s >>= 1) {
        if (k < s) { ra[k] += ra[k+s]; rb[k] += rb[k+s]; rw[k] += rw[k+s]; rc[k] += rc[k+s]; }
        __syncthreads();
    }
    if (k == 0) {
        g_cbsc[n] = ra[0] + ea_b1[n];
        g_cbth[n] = rb[0] + eu_b1[n];
        g_wcomp[n] = rw[0];
        if (n == 0) g_cconst[0] = rc[0] + ew_b[0];
    }
}

// convert W ([k][n] row-major, stride 256) to K-major fp16
__global__ void conv_w(const float* __restrict__ W, __half* __restrict__ out) {
    int idx = blockIdx.x * 256 + threadIdx.x;
    int n = idx >> 8, k = idx & 255;
    out[(size_t)n * H + k] = __float2half_rn(W[(size_t)k * H + n]);
}

__global__ void deg_kernel(const int* __restrict__ deg, const int* __restrict__ batch,
                           const int* __restrict__ heads, const int* __restrict__ tails) {
    int n = blockIdx.x * 256 + threadIdx.x;
    int d = deg[n];
    float inv = 1.f / (1.f + (float)d);
    g_inv[n] = inv;
    g_rs[n] = (d > 0) ? inv : 0.f;
    int b = batch[n];
    g_ish[n] = (heads[b] == n) ? 1.f : 0.f;
    g_ist[n] = (tails[b] == n) ? 1.f : 0.f;
}

__global__ void init_be_kernel(const float* __restrict__ ef, const float* __restrict__ gall) {
    int t = blockIdx.x * 256 + threadIdx.x;      // E*64 threads, float4 each
    int e = t >> 6, j4 = t & 63;
    float4 v;
    if (j4 < 48) v = *(const float4*)(ef + (size_t)e * 192 + j4 * 4);
    else         v = *(const float4*)(gall + (j4 - 48) * 4);
    *(float4*)(g_be + (size_t)e * H + j4 * 4) = v;
}

// ---------------- per-iteration small kernels ----------------

__global__ void init_iter_kernel(float* __restrict__ dst) {   // zero dst (N*H) + m/s
    int t = blockIdx.x * 256 + threadIdx.x;
    if (t < NN * H) dst[t] = 0.f;
    if (t < NN) { g_m[t] = 0.f; g_s[t] = 0.f; }
}

__global__ void segmax_kernel(const int* __restrict__ recv) {
    int e = blockIdx.x * 256 + threadIdx.x;
    atomicMax((int*)&g_m[recv[e]], __float_as_int(g_score[e]));   // scores > 0
}

__global__ void exsum_kernel(const int* __restrict__ recv) {
    int e = blockIdx.x * 256 + threadIdx.x;
    int r = recv[e];
    float ex = expf(g_score[e] - g_m[r]);
    g_ex[e] = ex;
    atomicAdd(&g_s[r], ex);
}

__global__ void scatter_kernel(const float* __restrict__ X, float* __restrict__ dst,
                               const int* __restrict__ recv) {
    int t = blockIdx.x * 256 + threadIdx.x;      // E*64 threads, 4 cols each
    int e = t >> 6, c = t & 63;
    int r = recv[e];
    float alpha = g_ex[e] / g_s[r];
    float4 b = *(const float4*)(X + (size_t)e * H + c * 4);
    float* d = dst + (size_t)r * H + c * 4;
    asm volatile("red.global.add.v4.f32 [%0], {%1, %2, %3, %4};"
                 :: "l"(d), "f"(alpha * b.x), "f"(alpha * b.y),
                    "f"(alpha * b.z), "f"(alpha * b.w) : "memory");
}

__global__ void finalize0_kernel() {             // t=0: b_v = agg / (1+deg)
    int t = blockIdx.x * 256 + threadIdx.x;      // N*H
    g_bv[t] *= g_inv[t >> 8];
}

// ---------------- mma.sync fp16 GEMM: CTA 64x256, warp 32x64, A split-2 ----------------
// MODE 0 SCORE : out_score = sigmoid(relu(A@B + bias) @ wv + wb)
// MODE 1 HIDDEN: out = relu(A@B + bias + U[src] + V[recv])
// MODE 2 NODEUV: out = A@B + ish[r]*fH + ist[r]*fT
// MODE 3 NODEBV: out = (A*inv[r])@B + rs[r]*bias

#define ASTRIDE 40
#define BSTRIDE 40
#define OFF_AHI 0
#define OFF_ALO 5120
#define OFF_BH  10240
#define OFF_SB1 30720
#define OFF_SWV 31744
#define OFF_RSUM 32768
#define OFF_SRC 33024
#define OFF_RECV 33280
#define OFF_R1 33536
#define OFF_R2 33792
#define SMEM_BYTES 34048

#define MMA_F16(d, a, b0, b1)                                               \
    asm volatile("mma.sync.aligned.m16n8k16.row.col.f32.f16.f16.f32 "       \
        "{%0,%1,%2,%3}, {%4,%5,%6,%7}, {%8,%9}, {%0,%1,%2,%3};"             \
        : "+f"((d)[0]), "+f"((d)[1]), "+f"((d)[2]), "+f"((d)[3])            \
        : "r"((a)[0]), "r"((a)[1]), "r"((a)[2]), "r"((a)[3]),               \
          "r"(b0), "r"(b1))

__device__ __forceinline__ uint32_t pack_hi(float x, float y, uint32_t& lo_out) {
    __half hx = __float2half_rn(x), hy = __float2half_rn(y);
    __half lx = __float2half_rn(x - __half2float(hx));
    __half ly = __float2half_rn(y - __half2float(hy));
    lo_out = (uint32_t)__half_as_ushort(lx) | ((uint32_t)__half_as_ushort(ly) << 16);
    return (uint32_t)__half_as_ushort(hx) | ((uint32_t)__half_as_ushort(hy) << 16);
}

template<int MODE>
__global__ __launch_bounds__(256) void mma_gemm(
    const float* __restrict__ A,
    const __half* __restrict__ Bg,
    const float* __restrict__ bias,
    const float* __restrict__ aux1, const float* __restrict__ aux2,
    const float* __restrict__ auxs,
    const int* __restrict__ srcp, const int* __restrict__ recvp,
    const float* __restrict__ rowv1, const float* __restrict__ rowv2,
    float* __restrict__ outp)
{
    extern __shared__ char smem[];
    __half* Ah = (__half*)(smem + OFF_AHI);
    __half* Al = (__half*)(smem + OFF_ALO);
    __half* Bh = (__half*)(smem + OFF_BH);
    float* sb1   = (float*)(smem + OFF_SB1);
    float* swv   = (float*)(smem + OFF_SWV);
    float* rsum  = (float*)(smem + OFF_RSUM);
    int*   s_src = (int*)(smem + OFF_SRC);
    int*   s_rcv = (int*)(smem + OFF_RECV);
    float* s_r1  = (float*)(smem + OFF_R1);
    float* s_r2  = (float*)(smem + OFF_R2);

    const int tid = threadIdx.x, lane = tid & 31, wid = tid >> 5;
    const int row0 = blockIdx.x * 64;
    const int mbase = (wid >> 2) * 32, nbase = (wid & 3) * 64;

    if (MODE != 2) sb1[tid] = bias[tid];
    if (MODE == 0) { swv[tid] = aux1[tid]; if (tid < 64) rsum[tid] = 0.f; }
    if (MODE == 1 && tid < 64) { s_src[tid] = srcp[row0 + tid]; s_rcv[tid] = recvp[row0 + tid]; }
    if ((MODE == 2 || MODE == 3) && tid < 64) {
        s_r1[tid] = rowv1[row0 + tid];
        s_r2[tid] = rowv2[row0 + tid];
    }
    __syncthreads();

    float acc[2][8][4];
    #pragma unroll
    for (int mf = 0; mf < 2; mf++)
        #pragma unroll
        for (int nf = 0; nf < 8; nf++)
            #pragma unroll
            for (int q = 0; q < 4; q++) acc[mf][nf][q] = 0.f;

    const int arow = tid >> 2, ac0 = (tid & 3) * 8;

    for (int kt = 0; kt < H; kt += 32) {
        // ---- stage A (fp32 -> hi/lo fp16) ----
        {
            float x[8];
            *(float4*)&x[0] = *(const float4*)(A + (size_t)(row0 + arow) * H + kt + ac0);
            *(float4*)&x[4] = *(const float4*)(A + (size_t)(row0 + arow) * H + kt + ac0 + 4);
            if (MODE == 3) {
                float sc = s_r1[arow];
                #pragma unroll
                for (int q = 0; q < 8; q++) x[q] *= sc;
            }
            uint4 uh, ul;
            uh.x = pack_hi(x[0], x[1], ul.x);
            uh.y = pack_hi(x[2], x[3], ul.y);
            uh.z = pack_hi(x[4], x[5], ul.z);
            uh.w = pack_hi(x[6], x[7], ul.w);
            *(uint4*)&Ah[arow * ASTRIDE + ac0] = uh;
            *(uint4*)&Al[arow * ASTRIDE + ac0] = ul;
        }
        // ---- stage B (fp16, 32 k per thread-row) ----
        {
            const __half* bsrc = Bg + (size_t)tid * H + kt;
            #pragma unroll
            for (int j = 0; j < 4; j++)
                *(uint4*)&Bh[tid * BSTRIDE + j * 8] = *(const uint4*)(bsrc + j * 8);
        }
        __syncthreads();
        #pragma unroll
        for (int ks = 0; ks < 2; ks++) {
            const int k0 = ks * 16 + (lane & 3) * 2;
            uint32_t ahi[2][4], alo[2][4];
            #pragma unroll
            for (int mf = 0; mf < 2; mf++) {
                int r = mbase + mf * 16 + (lane >> 2);
                ahi[mf][0] = *(uint32_t*)&Ah[r * ASTRIDE + k0];
                ahi[mf][1] = *(uint32_t*)&Ah[(r + 8) * ASTRIDE + k0];
                ahi[mf][2] = *(uint32_t*)&Ah[r * ASTRIDE + k0 + 8];
                ahi[mf][3] = *(uint32_t*)&Ah[(r + 8) * ASTRIDE + k0 + 8];
                alo[mf][0] = *(uint32_t*)&Al[r * ASTRIDE + k0];
                alo[mf][1] = *(uint32_t*)&Al[(r + 8) * ASTRIDE + k0];
                alo[mf][2] = *(uint32_t*)&Al[r * ASTRIDE + k0 + 8];
                alo[mf][3] = *(uint32_t*)&Al[(r + 8) * ASTRIDE + k0 + 8];
            }
            #pragma unroll
            for (int nf = 0; nf < 8; nf++) {
                int n = nbase + nf * 8 + (lane >> 2);
                uint32_t b0 = *(uint32_t*)&Bh[n * BSTRIDE + k0];
                uint32_t b1 = *(uint32_t*)&Bh[n * BSTRIDE + k0 + 8];
                #pragma unroll
                for (int mf = 0; mf < 2; mf++) {
                    MMA_F16(acc[mf][nf], ahi[mf], b0, b1);
                    MMA_F16(acc[mf][nf], alo[mf], b0, b1);
                }
            }
        }
        __syncthreads();
    }

    // ---- epilogues ----
    if (MODE == 0) {
        float part[2][2] = {{0.f, 0.f}, {0.f, 0.f}};
        #pragma unroll
        for (int mf = 0; mf < 2; mf++)
            #pragma unroll
            for (int nf = 0; nf < 8; nf++) {
                int c0 = nbase + nf * 8 + (lane & 3) * 2;
                float w0 = swv[c0], w1 = swv[c0 + 1];
                float bb0 = sb1[c0], bb1 = sb1[c0 + 1];
                float v0 = fmaxf(acc[mf][nf][0] + bb0, 0.f);
                float v1 = fmaxf(acc[mf][nf][1] + bb1, 0.f);
                float v2 = fmaxf(acc[mf][nf][2] + bb0, 0.f);
                float v3 = fmaxf(acc[mf][nf][3] + bb1, 0.f);
                part[mf][0] = fmaf(v0, w0, fmaf(v1, w1, part[mf][0]));
                part[mf][1] = fmaf(v2, w0, fmaf(v3, w1, part[mf][1]));
            }
        #pragma unroll
        for (int off = 1; off <= 2; off <<= 1)
            #pragma unroll
            for (int mf = 0; mf < 2; mf++) {
                part[mf][0] += __shfl_xor_sync(0xffffffffu, part[mf][0], off);
                part[mf][1] += __shfl_xor_sync(0xffffffffu, part[mf][1], off);
            }
        if ((lane & 3) == 0) {
            #pragma unroll
            for (int mf = 0; mf < 2; mf++) {
                atomicAdd(&rsum[mbase + mf * 16 + (lane >> 2)],     part[mf][0]);
                atomicAdd(&rsum[mbase + mf * 16 + (lane >> 2) + 8], part[mf][1]);
            }
        }
        __syncthreads();
        if (tid < 64)
            outp[row0 + tid] = 1.f / (1.f + expf(-(rsum[tid] + auxs[0])));
    } else {
        #pragma unroll
        for (int mf = 0; mf < 2; mf++)
            #pragma unroll
            for (int nf = 0; nf < 8; nf++) {
                int rA = mbase + mf * 16 + (lane >> 2);
                int rB = rA + 8;
                int c0 = nbase + nf * 8 + (lane & 3) * 2;
                float2 v0 = make_float2(acc[mf][nf][0], acc[mf][nf][1]);
                float2 v1 = make_float2(acc[mf][nf][2], acc[mf][nf][3]);
                if (MODE == 1) {
                    float bb0 = sb1[c0], bb1 = sb1[c0 + 1];
                    float2 ua = *(const float2*)(aux1 + (size_t)s_src[rA] * H + c0);
                    float2 va = *(const float2*)(aux2 + (size_t)s_rcv[rA] * H + c0);
                    float2 ub = *(const float2*)(aux1 + (size_t)s_src[rB] * H + c0);
                    float2 vb = *(const float2*)(aux2 + (size_t)s_rcv[rB] * H + c0);
                    v0.x = fmaxf(v0.x + bb0 + ua.x + va.x, 0.f);
                    v0.y = fmaxf(v0.y + bb1 + ua.y + va.y, 0.f);
                    v1.x = fmaxf(v1.x + bb0 + ub.x + vb.x, 0.f);
                    v1.y = fmaxf(v1.y + bb1 + ub.y + vb.y, 0.f);
                } else if (MODE == 2) {
                    float fh0 = __ldg(aux1 + c0), fh1 = __ldg(aux1 + c0 + 1);
                    float ft0 = __ldg(aux2 + c0), ft1 = __ldg(aux2 + c0 + 1);
                    v0.x += s_r1[rA] * fh0 + s_r2[rA] * ft0;
                    v0.y += s_r1[rA] * fh1 + s_r2[rA] * ft1;
                    v1.x += s_r1[rB] * fh0 + s_r2[rB] * ft0;
                    v1.y += s_r1[rB] * fh1 + s_r2[rB] * ft1;
                } else {  // MODE 3
                    float bb0 = sb1[c0], bb1 = sb1[c0 + 1];
                    v0.x += s_r2[rA] * bb0; v0.y += s_r2[rA] * bb1;
                    v1.x += s_r2[rB] * bb0; v1.y += s_r2[rB] * bb1;
                }
                *(float2*)(outp + (size_t)(row0 + rA) * H + c0) = v0;
                *(float2*)(outp + (size_t)(row0 + rB) * H + c0) = v1;
            }
    }
}

// ---------------- w_e matvec: out[e] = sigmoid(hidden[e]@wcomp + cconst) ----------------

__global__ void we_kernel(float* __restrict__ out) {
    __shared__ float wc[H];
    int tid = threadIdx.x, lane = tid & 31, wid = tid >> 5;
    wc[tid] = g_wcomp[tid];
    __syncthreads();
    int e = blockIdx.x * 8 + wid;
    const float* hrow = g_hidden + (size_t)e * H + lane * 8;
    float4 x0 = *(const float4*)hrow;
    float4 x1 = *(const float4*)(hrow + 4);
    const float* w = wc + lane * 8;
    float s = x0.x * w[0] + x0.y * w[1] + x0.z * w[2] + x0.w * w[3]
            + x1.x * w[4] + x1.y * w[5] + x1.z * w[6] + x1.w * w[7];
    #pragma unroll
    for (int off = 16; off > 0; off >>= 1) s += __shfl_xor_sync(0xffffffffu, s, off);
    if (lane == 0) out[e] = 1.f / (1.f + expf(-(s + g_cconst[0])));
}

// ---------------- graph readout ----------------

__global__ void gmax_kernel(const int* __restrict__ heads, const int* __restrict__ tails) {
    int g = blockIdx.x, j = threadIdx.x;
    float mx = -3.4e38f;
    int base = g * 256;
    for (int n = 0; n < 256; n++)
        mx = fmaxf(mx, g_bv[(size_t)(base + n) * H + j]);
    g_gG[g * 768 + j]       = mx;
    g_gG[g * 768 + 256 + j] = g_bv[(size_t)heads[g] * H + j];
    g_gG[g * 768 + 512 + j] = g_bv[(size_t)tails[g] * H + j];
}

__global__ void gmlp_kernel(const float* __restrict__ W1, const float* __restrict__ b1,
                            const float* __restrict__ w2, const float* __restrict__ b2) {
    __shared__ float row[768];
    __shared__ float red[256];
    int g = blockIdx.x, tid = threadIdx.x;
    for (int i = tid; i < 768; i += 256) row[i] = g_gG[g * 768 + i];
    __syncthreads();
    float h = b1[tid];
    for (int k = 0; k < 768; k++) h = fmaf(row[k], W1[(size_t)k * 256 + tid], h);
    h = fmaxf(h, 0.f);
    red[tid] = h * w2[tid];
    __syncthreads();
    for (int s = 128; s > 0; s >>= 1) {
        if (tid < s) red[tid] += red[tid + s];
        __syncthreads();
    }
    if (tid == 0) g_z[g] = red[0] + b2[0];
}

__global__ void gout_kernel(float* __restrict__ out) {
    __shared__ float zs[NG];
    int tid = threadIdx.x;
    if (tid < NG) zs[tid] = g_z[tid];
    __syncthreads();
    float m = -3.4e38f;
    for (int g = 0; g < NG; g++) m = fmaxf(m, zs[g]);
    float denom = 0.f;
    for (int g = 0; g < NG; g++) denom += expf(zs[g] - m);
    float acc = 0.f;
    for (int g = 0; g < NG; g++) acc += (expf(zs[g] - m) / denom) * g_gG[g * 768 + tid];
    out[tid] = acc;
}

// ---------------- launch ----------------

static float* dev_ptr(const void* sym) { void* p = nullptr; cudaGetSymbolAddress(&p, sym); return (float*)p; }

extern "C" void kernel_launch(void* const* d_in, const int* in_sizes, int n_in,
                              void* d_out, int out_size) {
    const float* ef     = (const float*)d_in[0];
    const float* gall   = (const float*)d_in[1];
    const float* ea_w1  = (const float*)d_in[2];
    const float* ea_b1  = (const float*)d_in[3];
    const float* ea_w2  = (const float*)d_in[4];
    const float* ea_b2  = (const float*)d_in[5];
    const float* eu_w1  = (const float*)d_in[6];
    const float* eu_b1  = (const float*)d_in[7];
    const float* eu_w2  = (const float*)d_in[8];
    const float* eu_b2  = (const float*)d_in[9];
    const float* gw_w1  = (const float*)d_in[10];
    const float* gw_b1  = (const float*)d_in[11];
    const float* gw_w2  = (const float*)d_in[12];
    const float* gw_b2  = (const float*)d_in[13];
    const float* ew_w   = (const float*)d_in[14];
    const float* ew_b   = (const float*)d_in[15];
    const int*   eidx   = (const int*)d_in[16];
    const int*   deg    = (const int*)d_in[17];
    const int*   batch  = (const int*)d_in[18];
    const int*   heads  = (const int*)d_in[19];
    const int*   tails  = (const int*)d_in[20];
    const int* src  = eidx;
    const int* recv = eidx + E_TOT;
    float* out = (float*)d_out;
    const float* w1c = eu_w1 + 516 * H;   // rows 516..771
    const float* w1a = eu_w1;             // rows 0..255 (+ flag rows 256,257)
    const float* w1b = eu_w1 + 258 * H;   // rows 258..513 (+ flag rows 514,515)

    cudaFuncSetAttribute(mma_gemm<0>, cudaFuncAttributeMaxDynamicSharedMemorySize, SMEM_BYTES);
    cudaFuncSetAttribute(mma_gemm<1>, cudaFuncAttributeMaxDynamicSharedMemorySize, SMEM_BYTES);
    cudaFuncSetAttribute(mma_gemm<2>, cudaFuncAttributeMaxDynamicSharedMemorySize, SMEM_BYTES);
    cudaFuncSetAttribute(mma_gemm<3>, cudaFuncAttributeMaxDynamicSharedMemorySize, SMEM_BYTES);

    float *p_Wsc = dev_ptr(g_Wsc), *p_Wth = dev_ptr(g_Wth);
    float *p_cbsc = dev_ptr(g_cbsc), *p_cbth = dev_ptr(g_cbth);
    float *p_be = dev_ptr(g_be), *p_hidden = dev_ptr(g_hidden);
    float *p_bv = dev_ptr(g_bv), *p_agg = dev_ptr(g_agg);
    float *p_U = dev_ptr(g_U), *p_V = dev_ptr(g_V);
    float *p_score = dev_ptr(g_score);
    float *p_inv = dev_ptr(g_inv), *p_rs = dev_ptr(g_rs);
    float *p_ish = dev_ptr(g_ish), *p_ist = dev_ptr(g_ist);
    __half *h_sc0 = (__half*)dev_ptr(g_h_sc0), *h_sc = (__half*)dev_ptr(g_h_sc);
    __half *h_th0 = (__half*)dev_ptr(g_h_th0), *h_th = (__half*)dev_ptr(g_h_th);
    __half *h_u = (__half*)dev_ptr(g_h_u), *h_v = (__half*)dev_ptr(g_h_v);
    __half *h_w2 = (__half*)dev_ptr(g_h_w2);

    // ---- prep ----
    deg_kernel<<<NN / 256, 256>>>(deg, batch, heads, tails);
    comp_mat<<<256, 256>>>(eu_w2, ea_w1, p_Wsc);
    comp_mat<<<256, 256>>>(eu_w2, w1c, p_Wth);
    comp_vec<<<256, 256>>>(eu_w2, eu_b2, ea_w1, ea_b1, w1c, eu_b1, ew_w, ew_b);
    conv_w<<<256, 256>>>(ea_w1, h_sc0);
    conv_w<<<256, 256>>>(p_Wsc, h_sc);
    conv_w<<<256, 256>>>(w1c, h_th0);
    conv_w<<<256, 256>>>(p_Wth, h_th);
    conv_w<<<256, 256>>>(w1a, h_u);
    conv_w<<<256, 256>>>(w1b, h_v);
    conv_w<<<256, 256>>>(eu_w2, h_w2);
    init_be_kernel<<<E_TOT / 4, 256>>>(ef, gall);

    for (int it = 0; it < 3; it++) {
        const float* Acur = (it == 0) ? p_be : p_hidden;
        float* aggdst = (it == 0) ? p_bv : p_agg;

        init_iter_kernel<<<(NN * H + 255) / 256, 256>>>(aggdst);
        // score
        mma_gemm<0><<<E_TOT / 64, 256, SMEM_BYTES>>>(
            Acur, (it == 0) ? h_sc0 : h_sc,
            (it == 0) ? ea_b1 : p_cbsc, ea_w2, nullptr, ea_b2,
            nullptr, nullptr, nullptr, nullptr, p_score);
        // softmax-aggregate
        segmax_kernel<<<E_TOT / 256, 256>>>(recv);
        exsum_kernel<<<E_TOT / 256, 256>>>(recv);
        scatter_kernel<<<(E_TOT * 64) / 256, 256>>>(Acur, aggdst, recv);
        if (it == 0)
            finalize0_kernel<<<(NN * H) / 256, 256>>>();
        else
            mma_gemm<3><<<NN / 64, 256, SMEM_BYTES>>>(
                p_agg, h_w2, eu_b2, nullptr, nullptr, nullptr,
                nullptr, nullptr, p_inv, p_rs, p_bv);
        // U, V node GEMMs
        mma_gemm<2><<<NN / 64, 256, SMEM_BYTES>>>(
            p_bv, h_u, nullptr, eu_w1 + 256 * H, eu_w1 + 257 * H, nullptr,
            nullptr, nullptr, p_ish, p_ist, p_U);
        mma_gemm<2><<<NN / 64, 256, SMEM_BYTES>>>(
            p_bv, h_v, nullptr, eu_w1 + 514 * H, eu_w1 + 515 * H, nullptr,
            nullptr, nullptr, p_ish, p_ist, p_V);
        // hidden
        mma_gemm<1><<<E_TOT / 64, 256, SMEM_BYTES>>>(
            Acur, (it == 0) ? h_th0 : h_th,
            (it == 0) ? eu_b1 : p_cbth, p_U, p_V, nullptr,
            src, recv, nullptr, nullptr, p_hidden);
    }

    we_kernel<<<E_TOT / 8, 256>>>(out);
    gmax_kernel<<<NG, 256>>>(heads, tails);
    gmlp_kernel<<<NG, 256>>>(gw_w1, gw_b1, gw_w2, gw_b2);
    gout_kernel<<<1, 768>>>(out + E_TOT);
}

// round 8
// speedup vs baseline: 7.2959x; 1.1853x over previous
#include <cuda_runtime.h>
#include <cuda_fp16.h>
#include <cstdint>
#include <math.h>

#define E_TOT 262144
#define NN    16384
#define H     256
#define NG    64

// ---------------- scratch (device globals; no allocation allowed) ----------------
__device__ float g_be[(size_t)E_TOT * H];       // b_e^0 (iter-0 edge state)
__device__ float g_hidden[(size_t)E_TOT * H];   // hidden_t (iters 0,1 only)
__device__ float g_ex[E_TOT];
__device__ float g_s[NN];
__device__ float g_bv[(size_t)NN * H];          // node state b_v
__device__ float g_agg[(size_t)NN * H];         // segsum(alpha*hidden)
__device__ float g_U[(size_t)NN * H];
__device__ float g_V[(size_t)NN * H];
__device__ float g_gG[NG * 768];
__device__ float g_z[NG];

// composed fp32 weights / vectors
__device__ float g_Wsc[H * H];    // W2 @ ea_w1
__device__ float g_Wth[H * H];    // W2 @ W1c
__device__ float g_cbsc[H];       // b2@ea_w1 + ea_b1
__device__ float g_cbth[H];       // b2@W1c + eu_b1
__device__ float g_wcomp[H];      // W2 @ ew_w
__device__ float g_cconst[1];     // b2@ew_w + ew_b
__device__ float g_inv[NN], g_rs[NN], g_ish[NN], g_ist[NN];

// fp16 weights, K-major B[n][k]
__device__ __half g_h_sc0[H*H];   // ea_w1
__device__ __half g_h_sc[H*H];    // Wsc
__device__ __half g_h_th0[H*H];   // W1c
__device__ __half g_h_th[H*H];    // Wth
__device__ __half g_h_u[H*H];     // W1a
__device__ __half g_h_v[H*H];     // W1b
__device__ __half g_h_w2[H*H];    // W2

// ---------------- prep kernels ----------------

__global__ void comp_mat(const float* __restrict__ L, const float* __restrict__ R,
                         float* __restrict__ C) {
    __shared__ float lrow[H];
    int k = blockIdx.x, n = threadIdx.x;
    lrow[n] = L[k * H + n];
    __syncthreads();
    float acc = 0.f;
    for (int j = 0; j < H; j++) acc = fmaf(lrow[j], R[j * H + n], acc);
    C[k * H + n] = acc;
}

__global__ void comp_vec(const float* __restrict__ eu_w2, const float* __restrict__ eu_b2,
                         const float* __restrict__ ea_w1, const float* __restrict__ ea_b1,
                         const float* __restrict__ w1c, const float* __restrict__ eu_b1,
                         const float* __restrict__ ew_w, const float* __restrict__ ew_b) {
    __shared__ float ra[H], rb[H], rw[H], rc[H];
    int n = blockIdx.x, k = threadIdx.x;
    float e2 = eu_b2[k];
    ra[k] = e2 * ea_w1[k * H + n];
    rb[k] = e2 * w1c[k * H + n];
    rw[k] = eu_w2[n * H + k] * ew_w[k];
    rc[k] = e2 * ew_w[k];
    __syncthreads();
    for (int s = 128; s > 0; s >>= 1) {
        if (k < s) { ra[k] += ra[k+s]; rb[k] += rb[k+s]; rw[k] += rw[k+s]; rc[k] += rc[k+s]; }
        __syncthreads();
    }
    if (k == 0) {
        g_cbsc[n] = ra[0] + ea_b1[n];
        g_cbth[n] = rb[0] + eu_b1[n];
        g_wcomp[n] = rw[0];
        if (n == 0) g_cconst[0] = rc[0] + ew_b[0];
    }
}

__global__ void conv_w(const float* __restrict__ W, __half* __restrict__ out) {
    int idx = blockIdx.x * 256 + threadIdx.x;
    int n = idx >> 8, k = idx & 255;
    out[(size_t)n * H + k] = __float2half_rn(W[(size_t)k * H + n]);
}

__global__ void deg_kernel(const int* __restrict__ deg, const int* __restrict__ batch,
                           const int* __restrict__ heads, const int* __restrict__ tails) {
    int n = blockIdx.x * 256 + threadIdx.x;
    int d = deg[n];
    float inv = 1.f / (1.f + (float)d);
    g_inv[n] = inv;
    g_rs[n] = (d > 0) ? inv : 0.f;
    int b = batch[n];
    g_ish[n] = (heads[b] == n) ? 1.f : 0.f;
    g_ist[n] = (tails[b] == n) ? 1.f : 0.f;
}

__global__ void init_be_kernel(const float* __restrict__ ef, const float* __restrict__ gall) {
    int t = blockIdx.x * 256 + threadIdx.x;
    int e = t >> 6, j4 = t & 63;
    float4 v;
    if (j4 < 48) v = *(const float4*)(ef + (size_t)e * 192 + j4 * 4);
    else         v = *(const float4*)(gall + (j4 - 48) * 4);
    *(float4*)(g_be + (size_t)e * H + j4 * 4) = v;
}

// ---------------- per-iteration small kernels ----------------

__global__ void init_iter_kernel(float* __restrict__ dst) {   // zero dst (N*H) + s
    int t = blockIdx.x * 256 + threadIdx.x;
    if (t < NN * H) dst[t] = 0.f;
    if (t < NN) g_s[t] = 0.f;
}

__global__ void scatter_kernel(const float* __restrict__ X, float* __restrict__ dst,
                               const int* __restrict__ recv) {
    int t = blockIdx.x * 256 + threadIdx.x;
    int e = t >> 6, c = t & 63;
    int r = recv[e];
    float alpha = g_ex[e] / g_s[r];
    float4 b = *(const float4*)(X + (size_t)e * H + c * 4);
    float* d = dst + (size_t)r * H + c * 4;
    asm volatile("red.global.add.v4.f32 [%0], {%1, %2, %3, %4};"
                 :: "l"(d), "f"(alpha * b.x), "f"(alpha * b.y),
                    "f"(alpha * b.z), "f"(alpha * b.w) : "memory");
}

__global__ void finalize0_kernel() {             // t=0: b_v = agg / (1+deg)
    int t = blockIdx.x * 256 + threadIdx.x;
    g_bv[t] *= g_inv[t >> 8];
}

// ---------------- mma.sync fp16 GEMM: CTA 64x256, warp 32x64, single-term ----------------
// MODE 0 SCORE   : ex[e] = exp(sigmoid(relu(A@B+bias)@wv+wb)); s[recv[e]] += ex  (no stores of hidden)
// MODE 1 HIDDEN  : out = relu(A@B + bias + U[src] + V[recv])
// MODE 2 NODEUV  : out = A@B + ish[r]*fH + ist[r]*fT
// MODE 3 NODEBV  : out = (A*inv[r])@B + rs[r]*bias
// MODE 4 HIDDENWE: w_e = sigmoid(relu(A@B + bias + U[src] + V[recv]) @ wv + wb)  (hidden not stored)

#define ASTRIDE 40
#define BSTRIDE 40
#define OFF_AH  0
#define OFF_BH  5120
#define OFF_SB1 25600
#define OFF_SWV 26624
#define OFF_RSUM 27648
#define OFF_SRC 27904
#define OFF_RECV 28160
#define OFF_R1 28416
#define OFF_R2 28672
#define SMEM_BYTES 28928

#define MMA_F16(d, a, b0, b1)                                               \
    asm volatile("mma.sync.aligned.m16n8k16.row.col.f32.f16.f16.f32 "       \
        "{%0,%1,%2,%3}, {%4,%5,%6,%7}, {%8,%9}, {%0,%1,%2,%3};"             \
        : "+f"((d)[0]), "+f"((d)[1]), "+f"((d)[2]), "+f"((d)[3])            \
        : "r"((a)[0]), "r"((a)[1]), "r"((a)[2]), "r"((a)[3]),               \
          "r"(b0), "r"(b1))

__device__ __forceinline__ uint32_t pack_h2(float x, float y) {
    __half2 h = __floats2half2_rn(x, y);
    return *(uint32_t*)&h;
}

template<int MODE>
__global__ __launch_bounds__(256) void mma_gemm(
    const float* __restrict__ A,
    const __half* __restrict__ Bg,
    const float* __restrict__ bias,
    const float* __restrict__ aux1, const float* __restrict__ aux2,
    const float* __restrict__ wvp,  const float* __restrict__ auxs,
    const int* __restrict__ srcp, const int* __restrict__ recvp,
    const float* __restrict__ rowv1, const float* __restrict__ rowv2,
    float* __restrict__ outp)
{
    extern __shared__ char smem[];
    __half* Ah = (__half*)(smem + OFF_AH);
    __half* Bh = (__half*)(smem + OFF_BH);
    float* sb1   = (float*)(smem + OFF_SB1);
    float* swv   = (float*)(smem + OFF_SWV);
    float* rsum  = (float*)(smem + OFF_RSUM);
    int*   s_src = (int*)(smem + OFF_SRC);
    int*   s_rcv = (int*)(smem + OFF_RECV);
    float* s_r1  = (float*)(smem + OFF_R1);
    float* s_r2  = (float*)(smem + OFF_R2);

    const int tid = threadIdx.x, lane = tid & 31, wid = tid >> 5;
    const int row0 = blockIdx.x * 64;
    const int mbase = (wid >> 2) * 32, nbase = (wid & 3) * 64;

    if (MODE != 2) sb1[tid] = bias[tid];
    if (MODE == 0 || MODE == 4) { swv[tid] = wvp[tid]; if (tid < 64) rsum[tid] = 0.f; }
    if ((MODE == 1 || MODE == 4) && tid < 64) {
        s_src[tid] = srcp[row0 + tid];
        s_rcv[tid] = recvp[row0 + tid];
    }
    if ((MODE == 2 || MODE == 3) && tid < 64) {
        s_r1[tid] = rowv1[row0 + tid];
        s_r2[tid] = rowv2[row0 + tid];
    }
    __syncthreads();

    float acc[2][8][4];
    #pragma unroll
    for (int mf = 0; mf < 2; mf++)
        #pragma unroll
        for (int nf = 0; nf < 8; nf++)
            #pragma unroll
            for (int q = 0; q < 4; q++) acc[mf][nf][q] = 0.f;

    const int arow = tid >> 2, ac0 = (tid & 3) * 8;

    for (int kt = 0; kt < H; kt += 32) {
        // ---- stage A (fp32 -> fp16) ----
        {
            float x[8];
            *(float4*)&x[0] = *(const float4*)(A + (size_t)(row0 + arow) * H + kt + ac0);
            *(float4*)&x[4] = *(const float4*)(A + (size_t)(row0 + arow) * H + kt + ac0 + 4);
            if (MODE == 3) {
                float sc = s_r1[arow];
                #pragma unroll
                for (int q = 0; q < 8; q++) x[q] *= sc;
            }
            uint4 u;
            u.x = pack_h2(x[0], x[1]);
            u.y = pack_h2(x[2], x[3]);
            u.z = pack_h2(x[4], x[5]);
            u.w = pack_h2(x[6], x[7]);
            *(uint4*)&Ah[arow * ASTRIDE + ac0] = u;
        }
        // ---- stage B (fp16, 32 k per thread-row) ----
        {
            const __half* bsrc = Bg + (size_t)tid * H + kt;
            #pragma unroll
            for (int j = 0; j < 4; j++)
                *(uint4*)&Bh[tid * BSTRIDE + j * 8] = *(const uint4*)(bsrc + j * 8);
        }
        __syncthreads();
        #pragma unroll
        for (int ks = 0; ks < 2; ks++) {
            const int k0 = ks * 16 + (lane & 3) * 2;
            uint32_t af[2][4];
            #pragma unroll
            for (int mf = 0; mf < 2; mf++) {
                int r = mbase + mf * 16 + (lane >> 2);
                af[mf][0] = *(uint32_t*)&Ah[r * ASTRIDE + k0];
                af[mf][1] = *(uint32_t*)&Ah[(r + 8) * ASTRIDE + k0];
                af[mf][2] = *(uint32_t*)&Ah[r * ASTRIDE + k0 + 8];
                af[mf][3] = *(uint32_t*)&Ah[(r + 8) * ASTRIDE + k0 + 8];
            }
            #pragma unroll
            for (int nf = 0; nf < 8; nf++) {
                int n = nbase + nf * 8 + (lane >> 2);
                uint32_t b0 = *(uint32_t*)&Bh[n * BSTRIDE + k0];
                uint32_t b1 = *(uint32_t*)&Bh[n * BSTRIDE + k0 + 8];
                #pragma unroll
                for (int mf = 0; mf < 2; mf++)
                    MMA_F16(acc[mf][nf], af[mf], b0, b1);
            }
        }
        __syncthreads();
    }

    // ---- epilogues ----
    if (MODE == 0 || MODE == 4) {
        float part[2][2] = {{0.f, 0.f}, {0.f, 0.f}};
        #pragma unroll
        for (int mf = 0; mf < 2; mf++)
            #pragma unroll
            for (int nf = 0; nf < 8; nf++) {
                int rA = mbase + mf * 16 + (lane >> 2);
                int rB = rA + 8;
                int c0 = nbase + nf * 8 + (lane & 3) * 2;
                float w0 = swv[c0], w1 = swv[c0 + 1];
                float bb0 = sb1[c0], bb1 = sb1[c0 + 1];
                float v0, v1, v2, v3;
                if (MODE == 0) {
                    v0 = fmaxf(acc[mf][nf][0] + bb0, 0.f);
                    v1 = fmaxf(acc[mf][nf][1] + bb1, 0.f);
                    v2 = fmaxf(acc[mf][nf][2] + bb0, 0.f);
                    v3 = fmaxf(acc[mf][nf][3] + bb1, 0.f);
                } else {
                    float2 ua = *(const float2*)(aux1 + (size_t)s_src[rA] * H + c0);
                    float2 va = *(const float2*)(aux2 + (size_t)s_rcv[rA] * H + c0);
                    float2 ub = *(const float2*)(aux1 + (size_t)s_src[rB] * H + c0);
                    float2 vb = *(const float2*)(aux2 + (size_t)s_rcv[rB] * H + c0);
                    v0 = fmaxf(acc[mf][nf][0] + bb0 + ua.x + va.x, 0.f);
                    v1 = fmaxf(acc[mf][nf][1] + bb1 + ua.y + va.y, 0.f);
                    v2 = fmaxf(acc[mf][nf][2] + bb0 + ub.x + vb.x, 0.f);
                    v3 = fmaxf(acc[mf][nf][3] + bb1 + ub.y + vb.y, 0.f);
                }
                part[mf][0] = fmaf(v0, w0, fmaf(v1, w1, part[mf][0]));
                part[mf][1] = fmaf(v2, w0, fmaf(v3, w1, part[mf][1]));
            }
        #pragma unroll
        for (int off = 1; off <= 2; off <<= 1)
            #pragma unroll
            for (int mf = 0; mf < 2; mf++) {
                part[mf][0] += __shfl_xor_sync(0xffffffffu, part[mf][0], off);
                part[mf][1] += __shfl_xor_sync(0xffffffffu, part[mf][1], off);
            }
        if ((lane & 3) == 0) {
            #pragma unroll
            for (int mf = 0; mf < 2; mf++) {
                atomicAdd(&rsum[mbase + mf * 16 + (lane >> 2)],     part[mf][0]);
                atomicAdd(&rsum[mbase + mf * 16 + (lane >> 2) + 8], part[mf][1]);
            }
        }
        __syncthreads();
        if (tid < 64) {
            float sg = 1.f / (1.f + expf(-(rsum[tid] + auxs[0])));
            if (MODE == 0) {
                float ex = expf(sg);
                g_ex[row0 + tid] = ex;
                atomicAdd(&g_s[recvp[row0 + tid]], ex);
            } else {
                outp[row0 + tid] = sg;
            }
        }
    } else {
        #pragma unroll
        for (int mf = 0; mf < 2; mf++)
            #pragma unroll
            for (int nf = 0; nf < 8; nf++) {
                int rA = mbase + mf * 16 + (lane >> 2);
                int rB = rA + 8;
                int c0 = nbase + nf * 8 + (lane & 3) * 2;
                float2 v0 = make_float2(acc[mf][nf][0], acc[mf][nf][1]);
                float2 v1 = make_float2(acc[mf][nf][2], acc[mf][nf][3]);
                if (MODE == 1) {
                    float bb0 = sb1[c0], bb1 = sb1[c0 + 1];
                    float2 ua = *(const float2*)(aux1 + (size_t)s_src[rA] * H + c0);
                    float2 va = *(const float2*)(aux2 + (size_t)s_rcv[rA] * H + c0);
                    float2 ub = *(const float2*)(aux1 + (size_t)s_src[rB] * H + c0);
                    float2 vb = *(const float2*)(aux2 + (size_t)s_rcv[rB] * H + c0);
                    v0.x = fmaxf(v0.x + bb0 + ua.x + va.x, 0.f);
                    v0.y = fmaxf(v0.y + bb1 + ua.y + va.y, 0.f);
                    v1.x = fmaxf(v1.x + bb0 + ub.x + vb.x, 0.f);
                    v1.y = fmaxf(v1.y + bb1 + ub.y + vb.y, 0.f);
                } else if (MODE == 2) {
                    float fh0 = __ldg(aux1 + c0), fh1 = __ldg(aux1 + c0 + 1);
                    float ft0 = __ldg(aux2 + c0), ft1 = __ldg(aux2 + c0 + 1);
                    v0.x += s_r1[rA] * fh0 + s_r2[rA] * ft0;
                    v0.y += s_r1[rA] * fh1 + s_r2[rA] * ft1;
                    v1.x += s_r1[rB] * fh0 + s_r2[rB] * ft0;
                    v1.y += s_r1[rB] * fh1 + s_r2[rB] * ft1;
                } else {  // MODE 3
                    float bb0 = sb1[c0], bb1 = sb1[c0 + 1];
                    v0.x += s_r2[rA] * bb0; v0.y += s_r2[rA] * bb1;
                    v1.x += s_r2[rB] * bb0; v1.y += s_r2[rB] * bb1;
                }
                *(float2*)(outp + (size_t)(row0 + rA) * H + c0) = v0;
                *(float2*)(outp + (size_t)(row0 + rB) * H + c0) = v1;
            }
    }
}

// ---------------- graph readout ----------------

__global__ void gmax_kernel(const int* __restrict__ heads, const int* __restrict__ tails) {
    int g = blockIdx.x, j = threadIdx.x;
    float mx = -3.4e38f;
    int base = g * 256;
    for (int n = 0; n < 256; n++)
        mx = fmaxf(mx, g_bv[(size_t)(base + n) * H + j]);
    g_gG[g * 768 + j]       = mx;
    g_gG[g * 768 + 256 + j] = g_bv[(size_t)heads[g] * H + j];
    g_gG[g * 768 + 512 + j] = g_bv[(size_t)tails[g] * H + j];
}

__global__ void gmlp_kernel(const float* __restrict__ W1, const float* __restrict__ b1,
                            const float* __restrict__ w2, const float* __restrict__ b2) {
    __shared__ float row[768];
    __shared__ float red[256];
    int g = blockIdx.x, tid = threadIdx.x;
    for (int i = tid; i < 768; i += 256) row[i] = g_gG[g * 768 + i];
    __syncthreads();
    float h = b1[tid];
    for (int k = 0; k < 768; k++) h = fmaf(row[k], W1[(size_t)k * 256 + tid], h);
    h = fmaxf(h, 0.f);
    red[tid] = h * w2[tid];
    __syncthreads();
    for (int s = 128; s > 0; s >>= 1) {
        if (tid < s) red[tid] += red[tid + s];
        __syncthreads();
    }
    if (tid == 0) g_z[g] = red[0] + b2[0];
}

__global__ void gout_kernel(float* __restrict__ out) {
    __shared__ float zs[NG];
    int tid = threadIdx.x;
    if (tid < NG) zs[tid] = g_z[tid];
    __syncthreads();
    float m = -3.4e38f;
    for (int g = 0; g < NG; g++) m = fmaxf(m, zs[g]);
    float denom = 0.f;
    for (int g = 0; g < NG; g++) denom += expf(zs[g] - m);
    float acc = 0.f;
    for (int g = 0; g < NG; g++) acc += (expf(zs[g] - m) / denom) * g_gG[g * 768 + tid];
    out[tid] = acc;
}

// ---------------- launch ----------------

static float* dev_ptr(const void* sym) { void* p = nullptr; cudaGetSymbolAddress(&p, sym); return (float*)p; }

extern "C" void kernel_launch(void* const* d_in, const int* in_sizes, int n_in,
                              void* d_out, int out_size) {
    const float* ef     = (const float*)d_in[0];
    const float* gall   = (const float*)d_in[1];
    const float* ea_w1  = (const float*)d_in[2];
    const float* ea_b1  = (const float*)d_in[3];
    const float* ea_w2  = (const float*)d_in[4];
    const float* ea_b2  = (const float*)d_in[5];
    const float* eu_w1  = (const float*)d_in[6];
    const float* eu_b1  = (const float*)d_in[7];
    const float* eu_w2  = (const float*)d_in[8];
    const float* eu_b2  = (const float*)d_in[9];
    const float* gw_w1  = (const float*)d_in[10];
    const float* gw_b1  = (const float*)d_in[11];
    const float* gw_w2  = (const float*)d_in[12];
    const float* gw_b2  = (const float*)d_in[13];
    const float* ew_w   = (const float*)d_in[14];
    const float* ew_b   = (const float*)d_in[15];
    const int*   eidx   = (const int*)d_in[16];
    const int*   deg    = (const int*)d_in[17];
    const int*   batch  = (const int*)d_in[18];
    const int*   heads  = (const int*)d_in[19];
    const int*   tails  = (const int*)d_in[20];
    const int* src  = eidx;
    const int* recv = eidx + E_TOT;
    float* out = (float*)d_out;
    const float* w1c = eu_w1 + 516 * H;
    const float* w1a = eu_w1;
    const float* w1b = eu_w1 + 258 * H;

    cudaFuncSetAttribute(mma_gemm<0>, cudaFuncAttributeMaxDynamicSharedMemorySize, SMEM_BYTES);
    cudaFuncSetAttribute(mma_gemm<1>, cudaFuncAttributeMaxDynamicSharedMemorySize, SMEM_BYTES);
    cudaFuncSetAttribute(mma_gemm<2>, cudaFuncAttributeMaxDynamicSharedMemorySize, SMEM_BYTES);
    cudaFuncSetAttribute(mma_gemm<3>, cudaFuncAttributeMaxDynamicSharedMemorySize, SMEM_BYTES);
    cudaFuncSetAttribute(mma_gemm<4>, cudaFuncAttributeMaxDynamicSharedMemorySize, SMEM_BYTES);

    float *p_Wsc = dev_ptr(g_Wsc), *p_Wth = dev_ptr(g_Wth);
    float *p_cbsc = dev_ptr(g_cbsc), *p_cbth = dev_ptr(g_cbth);
    float *p_be = dev_ptr(g_be), *p_hidden = dev_ptr(g_hidden);
    float *p_bv = dev_ptr(g_bv), *p_agg = dev_ptr(g_agg);
    float *p_U = dev_ptr(g_U), *p_V = dev_ptr(g_V);
    float *p_inv = dev_ptr(g_inv), *p_rs = dev_ptr(g_rs);
    float *p_ish = dev_ptr(g_ish), *p_ist = dev_ptr(g_ist);
    float *p_wcomp = dev_ptr(g_wcomp), *p_cconst = dev_ptr(g_cconst);
    __half *h_sc0 = (__half*)dev_ptr(g_h_sc0), *h_sc = (__half*)dev_ptr(g_h_sc);
    __half *h_th0 = (__half*)dev_ptr(g_h_th0), *h_th = (__half*)dev_ptr(g_h_th);
    __half *h_u = (__half*)dev_ptr(g_h_u), *h_v = (__half*)dev_ptr(g_h_v);
    __half *h_w2 = (__half*)dev_ptr(g_h_w2);

    // ---- prep ----
    deg_kernel<<<NN / 256, 256>>>(deg, batch, heads, tails);
    comp_mat<<<256, 256>>>(eu_w2, ea_w1, p_Wsc);
    comp_mat<<<256, 256>>>(eu_w2, w1c, p_Wth);
    comp_vec<<<256, 256>>>(eu_w2, eu_b2, ea_w1, ea_b1, w1c, eu_b1, ew_w, ew_b);
    conv_w<<<256, 256>>>(ea_w1, h_sc0);
    conv_w<<<256, 256>>>(p_Wsc, h_sc);
    conv_w<<<256, 256>>>(w1c, h_th0);
    conv_w<<<256, 256>>>(p_Wth, h_th);
    conv_w<<<256, 256>>>(w1a, h_u);
    conv_w<<<256, 256>>>(w1b, h_v);
    conv_w<<<256, 256>>>(eu_w2, h_w2);
    init_be_kernel<<<E_TOT / 4, 256>>>(ef, gall);

    for (int it = 0; it < 3; it++) {
        const float* Acur = (it == 0) ? p_be : p_hidden;
        float* aggdst = (it == 0) ? p_bv : p_agg;

        init_iter_kernel<<<(NN * H + 255) / 256, 256>>>(aggdst);
        // score -> ex + s (softmax max-pass eliminated: scores in (0,1))
        mma_gemm<0><<<E_TOT / 64, 256, SMEM_BYTES>>>(
            Acur, (it == 0) ? h_sc0 : h_sc,
            (it == 0) ? ea_b1 : p_cbsc, nullptr, nullptr, ea_w2, ea_b2,
            nullptr, recv, nullptr, nullptr, nullptr);
        // aggregate
        scatter_kernel<<<(E_TOT * 64) / 256, 256>>>(Acur, aggdst, recv);
        if (it == 0)
            finalize0_kernel<<<(NN * H) / 256, 256>>>();
        else
            mma_gemm<3><<<NN / 64, 256, SMEM_BYTES>>>(
                p_agg, h_w2, eu_b2, nullptr, nullptr, nullptr, nullptr,
                nullptr, nullptr, p_inv, p_rs, p_bv);
        // U, V node GEMMs
        mma_gemm<2><<<NN / 64, 256, SMEM_BYTES>>>(
            p_bv, h_u, nullptr, eu_w1 + 256 * H, eu_w1 + 257 * H, nullptr, nullptr,
            nullptr, nullptr, p_ish, p_ist, p_U);
        mma_gemm<2><<<NN / 64, 256, SMEM_BYTES>>>(
            p_bv, h_v, nullptr, eu_w1 + 514 * H, eu_w1 + 515 * H, nullptr, nullptr,
            nullptr, nullptr, p_ish, p_ist, p_V);
        // hidden (last iter: fused w_e, hidden never materialized)
        if (it < 2)
            mma_gemm<1><<<E_TOT / 64, 256, SMEM_BYTES>>>(
                Acur, (it == 0) ? h_th0 : h_th,
                (it == 0) ? eu_b1 : p_cbth, p_U, p_V, nullptr, nullptr,
                src, recv, nullptr, nullptr, p_hidden);
        else
            mma_gemm<4><<<E_TOT / 64, 256, SMEM_BYTES>>>(
                Acur, h_th, p_cbth, p_U, p_V, p_wcomp, p_cconst,
                src, recv, nullptr, nullptr, out);
    }

    gmax_kernel<<<NG, 256>>>(heads, tails);
    gmlp_kernel<<<NG, 256>>>(gw_w1, gw_b1, gw_w2, gw_b2);
    gout_kernel<<<1, 768>>>(out + E_TOT);
}

// round 9
// speedup vs baseline: 7.4707x; 1.0240x over previous
#include <cuda_runtime.h>
#include <cuda_fp16.h>
#include <cstdint>
#include <math.h>

#define E_TOT 262144
#define NN    16384
#define H     256
#define NG    64

// ---------------- scratch ----------------
__device__ __half g_be[(size_t)E_TOT * H];      // edge state, fp16
__device__ __half g_hidden[(size_t)E_TOT * H];  // hidden_t, fp16
__device__ float g_s[NN];
__device__ float g_bv[(size_t)NN * H];
__device__ float g_agg[(size_t)NN * H];
__device__ float g_U[(size_t)NN * H];
__device__ float g_V[(size_t)NN * H];
__device__ float g_gG[NG * 768];
__device__ float g_z[NG];

// composed fp32 weights / vectors
__device__ float g_Wsc[H * H];
__device__ float g_Wth[H * H];
__device__ float g_cbsc[H];
__device__ float g_cbth[H];
__device__ float g_wcomp[H];
__device__ float g_cconst[1];
__device__ float g_inv[NN], g_rs[NN], g_ish[NN], g_ist[NN];

// fp16 weights, K-major B[n][k]
__device__ __half g_h_sc0[H*H];
__device__ __half g_h_sc[H*H];
__device__ __half g_h_th0[H*H];
__device__ __half g_h_th[H*H];
__device__ __half g_h_u[H*H];
__device__ __half g_h_v[H*H];
__device__ __half g_h_w2[H*H];

// ---------------- prep kernels ----------------

__global__ void comp_mat(const float* __restrict__ L, const float* __restrict__ R,
                         float* __restrict__ C) {
    __shared__ float lrow[H];
    int k = blockIdx.x, n = threadIdx.x;
    lrow[n] = L[k * H + n];
    __syncthreads();
    float acc = 0.f;
    for (int j = 0; j < H; j++) acc = fmaf(lrow[j], R[j * H + n], acc);
    C[k * H + n] = acc;
}

__global__ void comp_vec(const float* __restrict__ eu_w2, const float* __restrict__ eu_b2,
                         const float* __restrict__ ea_w1, const float* __restrict__ ea_b1,
                         const float* __restrict__ w1c, const float* __restrict__ eu_b1,
                         const float* __restrict__ ew_w, const float* __restrict__ ew_b) {
    __shared__ float ra[H], rb[H], rw[H], rc[H];
    int n = blockIdx.x, k = threadIdx.x;
    float e2 = eu_b2[k];
    ra[k] = e2 * ea_w1[k * H + n];
    rb[k] = e2 * w1c[k * H + n];
    rw[k] = eu_w2[n * H + k] * ew_w[k];
    rc[k] = e2 * ew_w[k];
    __syncthreads();
    for (int s = 128; s > 0; s >>= 1) {
        if (k < s) { ra[k] += ra[k+s]; rb[k] += rb[k+s]; rw[k] += rw[k+s]; rc[k] += rc[k+s]; }
        __syncthreads();
    }
    if (k == 0) {
        g_cbsc[n] = ra[0] + ea_b1[n];
        g_cbth[n] = rb[0] + eu_b1[n];
        g_wcomp[n] = rw[0];
        if (n == 0) g_cconst[0] = rc[0] + ew_b[0];
    }
}

__global__ void conv_w(const float* __restrict__ W, __half* __restrict__ out) {
    int idx = blockIdx.x * 256 + threadIdx.x;
    int n = idx >> 8, k = idx & 255;
    out[(size_t)n * H + k] = __float2half_rn(W[(size_t)k * H + n]);
}

__global__ void deg_kernel(const int* __restrict__ deg, const int* __restrict__ batch,
                           const int* __restrict__ heads, const int* __restrict__ tails) {
    int n = blockIdx.x * 256 + threadIdx.x;
    int d = deg[n];
    float inv = 1.f / (1.f + (float)d);
    g_inv[n] = inv;
    g_rs[n] = (d > 0) ? inv : 0.f;
    int b = batch[n];
    g_ish[n] = (heads[b] == n) ? 1.f : 0.f;
    g_ist[n] = (tails[b] == n) ? 1.f : 0.f;
}

__global__ void init_be_kernel(const float* __restrict__ ef, const float* __restrict__ gall) {
    int t = blockIdx.x * 256 + threadIdx.x;      // E*32 threads, 8 halves each
    int e = t >> 5, j = t & 31;                  // chunk of 8 cols
    const float* srcp = (j < 24) ? (ef + (size_t)e * 192 + j * 8) : (gall + (j - 24) * 8);
    float4 a = *(const float4*)srcp;
    float4 b = *(const float4*)(srcp + 4);
    __half2 h0 = __floats2half2_rn(a.x, a.y), h1 = __floats2half2_rn(a.z, a.w);
    __half2 h2 = __floats2half2_rn(b.x, b.y), h3 = __floats2half2_rn(b.z, b.w);
    uint4 u = make_uint4(*(uint32_t*)&h0, *(uint32_t*)&h1, *(uint32_t*)&h2, *(uint32_t*)&h3);
    *(uint4*)(g_be + (size_t)e * H + j * 8) = u;
}

// ---------------- per-iteration small kernels ----------------

__global__ void init_iter_kernel(float* __restrict__ dst) {
    int t = blockIdx.x * 256 + threadIdx.x;
    if (t < NN * H) dst[t] = 0.f;
    if (t < NN) g_s[t] = 0.f;
}

__global__ void finalize0_kernel() {   // b_v = agg * inv / s  (unnormalized scatter)
    int t = blockIdx.x * 256 + threadIdx.x;
    int n = t >> 8;
    float s = g_s[n];
    float sc = (s > 0.f) ? g_inv[n] / s : 0.f;
    g_bv[t] = g_agg[t] * sc;
}

// ---------------- fused score GEMM + softmax + scatter ----------------
// ex[e] = exp(sigmoid(relu(A@B+bias)@wv+wb)); s[recv] += ex; agg[recv] += ex*A
// Full 64x256 fp16 A tile resident in smem; scatter runs from smem.

#define AFSTRIDE 264
#define S_OFF_A    0                    // 64*264*2   = 33792
#define S_OFF_B    33792                // 256*40*2   = 20480
#define S_OFF_SB1  54272
#define S_OFF_SWV  55296
#define S_OFF_RSUM 56320
#define S_OFF_SEX  56576
#define S_OFF_RCV  56832
#define S_SMEM     57088

#define BSTRIDE 40
#define ASTRIDE 40

#define MMA_F16(d, a, b0, b1)                                               \
    asm volatile("mma.sync.aligned.m16n8k16.row.col.f32.f16.f16.f32 "       \
        "{%0,%1,%2,%3}, {%4,%5,%6,%7}, {%8,%9}, {%0,%1,%2,%3};"             \
        : "+f"((d)[0]), "+f"((d)[1]), "+f"((d)[2]), "+f"((d)[3])            \
        : "r"((a)[0]), "r"((a)[1]), "r"((a)[2]), "r"((a)[3]),               \
          "r"(b0), "r"(b1))

__device__ __forceinline__ uint32_t pack_h2(float x, float y) {
    __half2 h = __floats2half2_rn(x, y);
    return *(uint32_t*)&h;
}

__global__ __launch_bounds__(256) void score_scatter(
    const __half* __restrict__ A, const __half* __restrict__ Bg,
    const float* __restrict__ bias, const float* __restrict__ wvp,
    const float* __restrict__ wbp,
    const int* __restrict__ recvp, float* __restrict__ aggdst)
{
    extern __shared__ char smem[];
    __half* Af = (__half*)(smem + S_OFF_A);
    __half* Bh = (__half*)(smem + S_OFF_B);
    float* sb1  = (float*)(smem + S_OFF_SB1);
    float* swv  = (float*)(smem + S_OFF_SWV);
    float* rsum = (float*)(smem + S_OFF_RSUM);
    float* sex  = (float*)(smem + S_OFF_SEX);
    int*   srcv = (int*)(smem + S_OFF_RCV);

    const int tid = threadIdx.x, lane = tid & 31, wid = tid >> 5;
    const int row0 = blockIdx.x * 64;
    const int mbase = (wid >> 2) * 32, nbase = (wid & 3) * 64;

    sb1[tid] = bias[tid];
    swv[tid] = wvp[tid];
    if (tid < 64) { rsum[tid] = 0.f; srcv[tid] = recvp[row0 + tid]; }

    // ---- load full A tile (64 x 256 halves) ----
    {
        int r = tid >> 2, c0 = (tid & 3) * 64;
        #pragma unroll
        for (int j = 0; j < 8; j++) {
            uint4 u = *(const uint4*)(A + (size_t)(row0 + r) * H + c0 + j * 8);
            *(uint4*)&Af[r * AFSTRIDE + c0 + j * 8] = u;
        }
    }

    float acc[2][8][4];
    #pragma unroll
    for (int mf = 0; mf < 2; mf++)
        #pragma unroll
        for (int nf = 0; nf < 8; nf++)
            #pragma unroll
            for (int q = 0; q < 4; q++) acc[mf][nf][q] = 0.f;

    for (int kt = 0; kt < H; kt += 32) {
        {
            const __half* bsrc = Bg + (size_t)tid * H + kt;
            #pragma unroll
            for (int j = 0; j < 4; j++)
                *(uint4*)&Bh[tid * BSTRIDE + j * 8] = *(const uint4*)(bsrc + j * 8);
        }
        __syncthreads();
        #pragma unroll
        for (int ks = 0; ks < 2; ks++) {
            const int k0 = kt + ks * 16 + (lane & 3) * 2;
            uint32_t af[2][4];
            #pragma unroll
            for (int mf = 0; mf < 2; mf++) {
                int r = mbase + mf * 16 + (lane >> 2);
                af[mf][0] = *(uint32_t*)&Af[r * AFSTRIDE + k0];
                af[mf][1] = *(uint32_t*)&Af[(r + 8) * AFSTRIDE + k0];
                af[mf][2] = *(uint32_t*)&Af[r * AFSTRIDE + k0 + 8];
                af[mf][3] = *(uint32_t*)&Af[(r + 8) * AFSTRIDE + k0 + 8];
            }
            const int kb0 = ks * 16 + (lane & 3) * 2;
            #pragma unroll
            for (int nf = 0; nf < 8; nf++) {
                int n = nbase + nf * 8 + (lane >> 2);
                uint32_t b0 = *(uint32_t*)&Bh[n * BSTRIDE + kb0];
                uint32_t b1 = *(uint32_t*)&Bh[n * BSTRIDE + kb0 + 8];
                #pragma unroll
                for (int mf = 0; mf < 2; mf++)
                    MMA_F16(acc[mf][nf], af[mf], b0, b1);
            }
        }
        __syncthreads();
    }

    // ---- epilogue: relu + dot + sigmoid + exp ----
    float part[2][2] = {{0.f, 0.f}, {0.f, 0.f}};
    #pragma unroll
    for (int mf = 0; mf < 2; mf++)
        #pragma unroll
        for (int nf = 0; nf < 8; nf++) {
            int c0 = nbase + nf * 8 + (lane & 3) * 2;
            float w0 = swv[c0], w1 = swv[c0 + 1];
            float bb0 = sb1[c0], bb1 = sb1[c0 + 1];
            float v0 = fmaxf(acc[mf][nf][0] + bb0, 0.f);
            float v1 = fmaxf(acc[mf][nf][1] + bb1, 0.f);
            float v2 = fmaxf(acc[mf][nf][2] + bb0, 0.f);
            float v3 = fmaxf(acc[mf][nf][3] + bb1, 0.f);
            part[mf][0] = fmaf(v0, w0, fmaf(v1, w1, part[mf][0]));
            part[mf][1] = fmaf(v2, w0, fmaf(v3, w1, part[mf][1]));
        }
    #pragma unroll
    for (int off = 1; off <= 2; off <<= 1)
        #pragma unroll
        for (int mf = 0; mf < 2; mf++) {
            part[mf][0] += __shfl_xor_sync(0xffffffffu, part[mf][0], off);
            part[mf][1] += __shfl_xor_sync(0xffffffffu, part[mf][1], off);
        }
    if ((lane & 3) == 0) {
        #pragma unroll
        for (int mf = 0; mf < 2; mf++) {
            atomicAdd(&rsum[mbase + mf * 16 + (lane >> 2)],     part[mf][0]);
            atomicAdd(&rsum[mbase + mf * 16 + (lane >> 2) + 8], part[mf][1]);
        }
    }
    __syncthreads();
    if (tid < 64) {
        float sg = 1.f / (1.f + expf(-(rsum[tid] + wbp[0])));
        float ex = expf(sg);
        sex[tid] = ex;
        atomicAdd(&g_s[srcv[tid]], ex);
    }
    __syncthreads();

    // ---- scatter ex*A from smem (unnormalized; divide by s at node level) ----
    {
        int r = tid >> 2, c0 = (tid & 3) * 64;
        float exv = sex[r];
        float* drow = aggdst + (size_t)srcv[r] * H + c0;
        const __half* arow = Af + r * AFSTRIDE + c0;
        #pragma unroll
        for (int j = 0; j < 16; j++) {
            float2 f0 = __half22float2(*(const __half2*)(arow + j * 4));
            float2 f1 = __half22float2(*(const __half2*)(arow + j * 4 + 2));
            asm volatile("red.global.add.v4.f32 [%0], {%1, %2, %3, %4};"
                         :: "l"(drow + j * 4), "f"(exv * f0.x), "f"(exv * f0.y),
                            "f"(exv * f1.x), "f"(exv * f1.y) : "memory");
        }
    }
}

// ---------------- mma.sync fp16 GEMM: CTA 64x256, warp 32x64 ----------------
// MODE 1 HIDDEN  : outh = relu(A@B + bias + U[src] + V[recv])        A fp16, out fp16
// MODE 2 NODEUV  : outf = A@B + ish[r]*fH + ist[r]*fT                A fp32
// MODE 3 NODEBV  : outf = (A*inv[r]/s[r])@B + rs[r]*bias             A fp32
// MODE 4 HIDDENWE: w_e  = sigmoid(relu(A@B+bias+U[src]+V[recv])@wv+wb)  A fp16

#define OFF_AH  0
#define OFF_BH  5120
#define OFF_SB1 25600
#define OFF_SWV 26624
#define OFF_RSUM 27648
#define OFF_SRC 27904
#define OFF_RECV 28160
#define OFF_R1 28416
#define OFF_R2 28672
#define SMEM_BYTES 28928

template<int MODE>
__global__ __launch_bounds__(256) void mma_gemm(
    const void* __restrict__ Avp,
    const __half* __restrict__ Bg,
    const float* __restrict__ bias,
    const float* __restrict__ aux1, const float* __restrict__ aux2,
    const float* __restrict__ wvp,  const float* __restrict__ auxs,
    const int* __restrict__ srcp, const int* __restrict__ recvp,
    const float* __restrict__ rowv1, const float* __restrict__ rowv2,
    void* __restrict__ outvp)
{
    extern __shared__ char smem[];
    __half* Ah = (__half*)(smem + OFF_AH);
    __half* Bh = (__half*)(smem + OFF_BH);
    float* sb1   = (float*)(smem + OFF_SB1);
    float* swv   = (float*)(smem + OFF_SWV);
    float* rsum  = (float*)(smem + OFF_RSUM);
    int*   s_src = (int*)(smem + OFF_SRC);
    int*   s_rcv = (int*)(smem + OFF_RECV);
    float* s_r1  = (float*)(smem + OFF_R1);
    float* s_r2  = (float*)(smem + OFF_R2);

    const int tid = threadIdx.x, lane = tid & 31, wid = tid >> 5;
    const int row0 = blockIdx.x * 64;
    const int mbase = (wid >> 2) * 32, nbase = (wid & 3) * 64;

    if (MODE != 2) sb1[tid] = bias[tid];
    if (MODE == 4) { swv[tid] = wvp[tid]; if (tid < 64) rsum[tid] = 0.f; }
    if ((MODE == 1 || MODE == 4) && tid < 64) {
        s_src[tid] = srcp[row0 + tid];
        s_rcv[tid] = recvp[row0 + tid];
    }
    if (MODE == 2 && tid < 64) {
        s_r1[tid] = rowv1[row0 + tid];
        s_r2[tid] = rowv2[row0 + tid];
    }
    if (MODE == 3 && tid < 64) {
        int n = row0 + tid;
        float s = g_s[n];
        s_r1[tid] = (s > 0.f) ? rowv1[n] / s : 0.f;   // inv/s
        s_r2[tid] = rowv2[n];                          // rs
    }
    __syncthreads();

    float acc[2][8][4];
    #pragma unroll
    for (int mf = 0; mf < 2; mf++)
        #pragma unroll
        for (int nf = 0; nf < 8; nf++)
            #pragma unroll
            for (int q = 0; q < 4; q++) acc[mf][nf][q] = 0.f;

    const int arow = tid >> 2, ac0 = (tid & 3) * 8;

    for (int kt = 0; kt < H; kt += 32) {
        // ---- stage A ----
        if (MODE == 1 || MODE == 4) {
            const __half* Ag = (const __half*)Avp;
            uint4 u = *(const uint4*)(Ag + (size_t)(row0 + arow) * H + kt + ac0);
            *(uint4*)&Ah[arow * ASTRIDE + ac0] = u;
        } else {
            const float* Ag = (const float*)Avp;
            float x[8];
            *(float4*)&x[0] = *(const float4*)(Ag + (size_t)(row0 + arow) * H + kt + ac0);
            *(float4*)&x[4] = *(const float4*)(Ag + (size_t)(row0 + arow) * H + kt + ac0 + 4);
            if (MODE == 3) {
                float sc = s_r1[arow];
                #pragma unroll
                for (int q = 0; q < 8; q++) x[q] *= sc;
            }
            uint4 u;
            u.x = pack_h2(x[0], x[1]);
            u.y = pack_h2(x[2], x[3]);
            u.z = pack_h2(x[4], x[5]);
            u.w = pack_h2(x[6], x[7]);
            *(uint4*)&Ah[arow * ASTRIDE + ac0] = u;
        }
        // ---- stage B ----
        {
            const __half* bsrc = Bg + (size_t)tid * H + kt;
            #pragma unroll
            for (int j = 0; j < 4; j++)
                *(uint4*)&Bh[tid * BSTRIDE + j * 8] = *(const uint4*)(bsrc + j * 8);
        }
        __syncthreads();
        #pragma unroll
        for (int ks = 0; ks < 2; ks++) {
            const int k0 = ks * 16 + (lane & 3) * 2;
            uint32_t af[2][4];
            #pragma unroll
            for (int mf = 0; mf < 2; mf++) {
                int r = mbase + mf * 16 + (lane >> 2);
                af[mf][0] = *(uint32_t*)&Ah[r * ASTRIDE + k0];
                af[mf][1] = *(uint32_t*)&Ah[(r + 8) * ASTRIDE + k0];
                af[mf][2] = *(uint32_t*)&Ah[r * ASTRIDE + k0 + 8];
                af[mf][3] = *(uint32_t*)&Ah[(r + 8) * ASTRIDE + k0 + 8];
            }
            #pragma unroll
            for (int nf = 0; nf < 8; nf++) {
                int n = nbase + nf * 8 + (lane >> 2);
                uint32_t b0 = *(uint32_t*)&Bh[n * BSTRIDE + k0];
                uint32_t b1 = *(uint32_t*)&Bh[n * BSTRIDE + k0 + 8];
                #pragma unroll
                for (int mf = 0; mf < 2; mf++)
                    MMA_F16(acc[mf][nf], af[mf], b0, b1);
            }
        }
        __syncthreads();
    }

    // ---- epilogues ----
    if (MODE == 4) {
        float part[2][2] = {{0.f, 0.f}, {0.f, 0.f}};
        #pragma unroll
        for (int mf = 0; mf < 2; mf++)
            #pragma unroll
            for (int nf = 0; nf < 8; nf++) {
                int rA = mbase + mf * 16 + (lane >> 2);
                int rB = rA + 8;
                int c0 = nbase + nf * 8 + (lane & 3) * 2;
                float w0 = swv[c0], w1 = swv[c0 + 1];
                float bb0 = sb1[c0], bb1 = sb1[c0 + 1];
                float2 ua = *(const float2*)(aux1 + (size_t)s_src[rA] * H + c0);
                float2 va = *(const float2*)(aux2 + (size_t)s_rcv[rA] * H + c0);
                float2 ub = *(const float2*)(aux1 + (size_t)s_src[rB] * H + c0);
                float2 vb = *(const float2*)(aux2 + (size_t)s_rcv[rB] * H + c0);
                float v0 = fmaxf(acc[mf][nf][0] + bb0 + ua.x + va.x, 0.f);
                float v1 = fmaxf(acc[mf][nf][1] + bb1 + ua.y + va.y, 0.f);
                float v2 = fmaxf(acc[mf][nf][2] + bb0 + ub.x + vb.x, 0.f);
                float v3 = fmaxf(acc[mf][nf][3] + bb1 + ub.y + vb.y, 0.f);
                part[mf][0] = fmaf(v0, w0, fmaf(v1, w1, part[mf][0]));
                part[mf][1] = fmaf(v2, w0, fmaf(v3, w1, part[mf][1]));
            }
        #pragma unroll
        for (int off = 1; off <= 2; off <<= 1)
            #pragma unroll
            for (int mf = 0; mf < 2; mf++) {
                part[mf][0] += __shfl_xor_sync(0xffffffffu, part[mf][0], off);
                part[mf][1] += __shfl_xor_sync(0xffffffffu, part[mf][1], off);
            }
        if ((lane & 3) == 0) {
            #pragma unroll
            for (int mf = 0; mf < 2; mf++) {
                atomicAdd(&rsum[mbase + mf * 16 + (lane >> 2)],     part[mf][0]);
                atomicAdd(&rsum[mbase + mf * 16 + (lane >> 2) + 8], part[mf][1]);
            }
        }
        __syncthreads();
        if (tid < 64)
            ((float*)outvp)[row0 + tid] = 1.f / (1.f + expf(-(rsum[tid] + auxs[0])));
    } else {
        #pragma unroll
        for (int mf = 0; mf < 2; mf++)
            #pragma unroll
            for (int nf = 0; nf < 8; nf++) {
                int rA = mbase + mf * 16 + (lane >> 2);
                int rB = rA + 8;
                int c0 = nbase + nf * 8 + (lane & 3) * 2;
                float2 v0 = make_float2(acc[mf][nf][0], acc[mf][nf][1]);
                float2 v1 = make_float2(acc[mf][nf][2], acc[mf][nf][3]);
                if (MODE == 1) {
                    float bb0 = sb1[c0], bb1 = sb1[c0 + 1];
                    float2 ua = *(const float2*)(aux1 + (size_t)s_src[rA] * H + c0);
                    float2 va = *(const float2*)(aux2 + (size_t)s_rcv[rA] * H + c0);
                    float2 ub = *(const float2*)(aux1 + (size_t)s_src[rB] * H + c0);
                    float2 vb = *(const float2*)(aux2 + (size_t)s_rcv[rB] * H + c0);
                    v0.x = fmaxf(v0.x + bb0 + ua.x + va.x, 0.f);
                    v0.y = fmaxf(v0.y + bb1 + ua.y + va.y, 0.f);
                    v1.x = fmaxf(v1.x + bb0 + ub.x + vb.x, 0.f);
                    v1.y = fmaxf(v1.y + bb1 + ub.y + vb.y, 0.f);
                    __half* outh = (__half*)outvp;
                    *(uint32_t*)(outh + (size_t)(row0 + rA) * H + c0) = pack_h2(v0.x, v0.y);
                    *(uint32_t*)(outh + (size_t)(row0 + rB) * H + c0) = pack_h2(v1.x, v1.y);
                } else {
                    if (MODE == 2) {
                        float fh0 = __ldg(aux1 + c0), fh1 = __ldg(aux1 + c0 + 1);
                        float ft0 = __ldg(aux2 + c0), ft1 = __ldg(aux2 + c0 + 1);
                        v0.x += s_r1[rA] * fh0 + s_r2[rA] * ft0;
                        v0.y += s_r1[rA] * fh1 + s_r2[rA] * ft1;
                        v1.x += s_r1[rB] * fh0 + s_r2[rB] * ft0;
                        v1.y += s_r1[rB] * fh1 + s_r2[rB] * ft1;
                    } else {  // MODE 3
                        float bb0 = sb1[c0], bb1 = sb1[c0 + 1];
                        v0.x += s_r2[rA] * bb0; v0.y += s_r2[rA] * bb1;
                        v1.x += s_r2[rB] * bb0; v1.y += s_r2[rB] * bb1;
                    }
                    float* outf = (float*)outvp;
                    *(float2*)(outf + (size_t)(row0 + rA) * H + c0) = v0;
                    *(float2*)(outf + (size_t)(row0 + rB) * H + c0) = v1;
                }
            }
    }
}

// ---------------- graph readout ----------------

__global__ void gmax_kernel(const int* __restrict__ heads, const int* __restrict__ tails) {
    int g = blockIdx.x, j = threadIdx.x;
    float mx = -3.4e38f;
    int base = g * 256;
    for (int n = 0; n < 256; n++)
        mx = fmaxf(mx, g_bv[(size_t)(base + n) * H + j]);
    g_gG[g * 768 + j]       = mx;
    g_gG[g * 768 + 256 + j] = g_bv[(size_t)heads[g] * H + j];
    g_gG[g * 768 + 512 + j] = g_bv[(size_t)tails[g] * H + j];
}

__global__ void gmlp_kernel(const float* __restrict__ W1, const float* __restrict__ b1,
                            const float* __restrict__ w2, const float* __restrict__ b2) {
    __shared__ float row[768];
    __shared__ float red[256];
    int g = blockIdx.x, tid = threadIdx.x;
    for (int i = tid; i < 768; i += 256) row[i] = g_gG[g * 768 + i];
    __syncthreads();
    float h = b1[tid];
    for (int k = 0; k < 768; k++) h = fmaf(row[k], W1[(size_t)k * 256 + tid], h);
    h = fmaxf(h, 0.f);
    red[tid] = h * w2[tid];
    __syncthreads();
    for (int s = 128; s > 0; s >>= 1) {
        if (tid < s) red[tid] += red[tid + s];
        __syncthreads();
    }
    if (tid == 0) g_z[g] = red[0] + b2[0];
}

__global__ void gout_kernel(float* __restrict__ out) {
    __shared__ float zs[NG];
    int tid = threadIdx.x;
    if (tid < NG) zs[tid] = g_z[tid];
    __syncthreads();
    float m = -3.4e38f;
    for (int g = 0; g < NG; g++) m = fmaxf(m, zs[g]);
    float denom = 0.f;
    for (int g = 0; g < NG; g++) denom += expf(zs[g] - m);
    float acc = 0.f;
    for (int g = 0; g < NG; g++) acc += (expf(zs[g] - m) / denom) * g_gG[g * 768 + tid];
    out[tid] = acc;
}

// ---------------- launch ----------------

static float* dev_ptr(const void* sym) { void* p = nullptr; cudaGetSymbolAddress(&p, sym); return (float*)p; }

extern "C" void kernel_launch(void* const* d_in, const int* in_sizes, int n_in,
                              void* d_out, int out_size) {
    const float* ef     = (const float*)d_in[0];
    const float* gall   = (const float*)d_in[1];
    const float* ea_w1  = (const float*)d_in[2];
    const float* ea_b1  = (const float*)d_in[3];
    const float* ea_w2  = (const float*)d_in[4];
    const float* ea_b2  = (const float*)d_in[5];
    const float* eu_w1  = (const float*)d_in[6];
    const float* eu_b1  = (const float*)d_in[7];
    const float* eu_w2  = (const float*)d_in[8];
    const float* eu_b2  = (const float*)d_in[9];
    const float* gw_w1  = (const float*)d_in[10];
    const float* gw_b1  = (const float*)d_in[11];
    const float* gw_w2  = (const float*)d_in[12];
    const float* gw_b2  = (const float*)d_in[13];
    const float* ew_w   = (const float*)d_in[14];
    const float* ew_b   = (const float*)d_in[15];
    const int*   eidx   = (const int*)d_in[16];
    const int*   deg    = (const int*)d_in[17];
    const int*   batch  = (const int*)d_in[18];
    const int*   heads  = (const int*)d_in[19];
    const int*   tails  = (const int*)d_in[20];
    const int* src  = eidx;
    const int* recv = eidx + E_TOT;
    float* out = (float*)d_out;
    const float* w1c = eu_w1 + 516 * H;
    const float* w1a = eu_w1;
    const float* w1b = eu_w1 + 258 * H;

    cudaFuncSetAttribute(score_scatter, cudaFuncAttributeMaxDynamicSharedMemorySize, S_SMEM);
    cudaFuncSetAttribute(mma_gemm<1>, cudaFuncAttributeMaxDynamicSharedMemorySize, SMEM_BYTES);
    cudaFuncSetAttribute(mma_gemm<2>, cudaFuncAttributeMaxDynamicSharedMemorySize, SMEM_BYTES);
    cudaFuncSetAttribute(mma_gemm<3>, cudaFuncAttributeMaxDynamicSharedMemorySize, SMEM_BYTES);
    cudaFuncSetAttribute(mma_gemm<4>, cudaFuncAttributeMaxDynamicSharedMemorySize, SMEM_BYTES);

    float *p_Wsc = dev_ptr(g_Wsc), *p_Wth = dev_ptr(g_Wth);
    float *p_cbsc = dev_ptr(g_cbsc), *p_cbth = dev_ptr(g_cbth);
    __half *p_be = (__half*)dev_ptr(g_be), *p_hidden = (__half*)dev_ptr(g_hidden);
    float *p_bv = dev_ptr(g_bv), *p_agg = dev_ptr(g_agg);
    float *p_U = dev_ptr(g_U), *p_V = dev_ptr(g_V);
    float *p_inv = dev_ptr(g_inv), *p_rs = dev_ptr(g_rs);
    float *p_ish = dev_ptr(g_ish), *p_ist = dev_ptr(g_ist);
    float *p_wcomp = dev_ptr(g_wcomp), *p_cconst = dev_ptr(g_cconst);
    __half *h_sc0 = (__half*)dev_ptr(g_h_sc0), *h_sc = (__half*)dev_ptr(g_h_sc);
    __half *h_th0 = (__half*)dev_ptr(g_h_th0), *h_th = (__half*)dev_ptr(g_h_th);
    __half *h_u = (__half*)dev_ptr(g_h_u), *h_v = (__half*)dev_ptr(g_h_v);
    __half *h_w2 = (__half*)dev_ptr(g_h_w2);

    // ---- prep ----
    deg_kernel<<<NN / 256, 256>>>(deg, batch, heads, tails);
    comp_mat<<<256, 256>>>(eu_w2, ea_w1, p_Wsc);
    comp_mat<<<256, 256>>>(eu_w2, w1c, p_Wth);
    comp_vec<<<256, 256>>>(eu_w2, eu_b2, ea_w1, ea_b1, w1c, eu_b1, ew_w, ew_b);
    conv_w<<<256, 256>>>(ea_w1, h_sc0);
    conv_w<<<256, 256>>>(p_Wsc, h_sc);
    conv_w<<<256, 256>>>(w1c, h_th0);
    conv_w<<<256, 256>>>(p_Wth, h_th);
    conv_w<<<256, 256>>>(w1a, h_u);
    conv_w<<<256, 256>>>(w1b, h_v);
    conv_w<<<256, 256>>>(eu_w2, h_w2);
    init_be_kernel<<<E_TOT / 8, 256>>>(ef, gall);

    for (int it = 0; it < 3; it++) {
        const __half* Acur = (it == 0) ? p_be : p_hidden;
        float* aggdst = (it == 0) ? p_agg : p_agg;   // always unnormalized into g_agg

        init_iter_kernel<<<(NN * H + 255) / 256, 256>>>(p_agg);
        // fused score + softmax-denominator + scatter (unnormalized)
        score_scatter<<<E_TOT / 64, 256, S_SMEM>>>(
            Acur, (it == 0) ? h_sc0 : h_sc,
            (it == 0) ? ea_b1 : p_cbsc, ea_w2, ea_b2, recv, aggdst);
        // node state
        if (it == 0)
            finalize0_kernel<<<(NN * H) / 256, 256>>>();
        else
            mma_gemm<3><<<NN / 64, 256, SMEM_BYTES>>>(
                p_agg, h_w2, eu_b2, nullptr, nullptr, nullptr, nullptr,
                nullptr, nullptr, p_inv, p_rs, p_bv);
        // U, V node GEMMs
        mma_gemm<2><<<NN / 64, 256, SMEM_BYTES>>>(
            p_bv, h_u, nullptr, eu_w1 + 256 * H, eu_w1 + 257 * H, nullptr, nullptr,
            nullptr, nullptr, p_ish, p_ist, p_U);
        mma_gemm<2><<<NN / 64, 256, SMEM_BYTES>>>(
            p_bv, h_v, nullptr, eu_w1 + 514 * H, eu_w1 + 515 * H, nullptr, nullptr,
            nullptr, nullptr, p_ish, p_ist, p_V);
        // hidden (last iter: fused w_e)
        if (it < 2)
            mma_gemm<1><<<E_TOT / 64, 256, SMEM_BYTES>>>(
                Acur, (it == 0) ? h_th0 : h_th,
                (it == 0) ? eu_b1 : p_cbth, p_U, p_V, nullptr, nullptr,
                src, recv, nullptr, nullptr, p_hidden);
        else
            mma_gemm<4><<<E_TOT / 64, 256, SMEM_BYTES>>>(
                Acur, h_th, p_cbth, p_U, p_V, p_wcomp, p_cconst,
                src, recv, nullptr, nullptr, out);
    }

    gmax_kernel<<<NG, 256>>>(heads, tails);
    gmlp_kernel<<<NG, 256>>>(gw_w1, gw_b1, gw_w2, gw_b2);
    gout_kernel<<<1, 768>>>(out + E_TOT);
}

// round 11
// speedup vs baseline: 7.6977x; 1.0304x over previous
#include <cuda_runtime.h>
#include <cuda_fp16.h>
#include <cstdint>
#include <math.h>

#define E_TOT 262144
#define NN    16384
#define H     256
#define NG    64

// ---------------- scratch ----------------
__device__ __half g_be[(size_t)E_TOT * H];      // edge state (iter 0), fp16
__device__ __half g_hidden[(size_t)E_TOT * H];  // hidden_t, fp16
__device__ __half g_pre[(size_t)E_TOT * H];     // hidden pre-activation (no U/V), fp16
__device__ float g_s[NN];
__device__ float g_bv[(size_t)NN * H];
__device__ float g_agg[(size_t)NN * H];
__device__ float g_U[(size_t)NN * H];
__device__ float g_V[(size_t)NN * H];
__device__ float g_gG[NG * 768];
__device__ float g_z[NG];

// composed fp32 weights / vectors
__device__ float g_Wsc[H * H];    // W2 @ ea_w1
__device__ float g_Wth[H * H];    // W2 @ W1c
__device__ float g_WU2[H * H];    // W2 @ W1a
__device__ float g_WV2[H * H];    // W2 @ W1b
__device__ float g_cbsc[H];       // b2@ea_w1 + ea_b1
__device__ float g_cbth[H];       // b2@W1c + eu_b1
__device__ float g_cU[H];         // b2@W1a
__device__ float g_cV[H];         // b2@W1b
__device__ float g_wcomp[H];      // W2 @ ew_w
__device__ float g_cconst[1];     // b2@ew_w + ew_b
__device__ float g_inv[NN], g_rs[NN], g_ish[NN], g_ist[NN];

// fp16 weights, K-major B[n][k]
__device__ __half g_h_sc0[H*H];   // ea_w1
__device__ __half g_h_sc[H*H];    // Wsc
__device__ __half g_h_th0[H*H];   // W1c
__device__ __half g_h_th[H*H];    // Wth
__device__ __half g_h_u[H*H];     // W1a
__device__ __half g_h_v[H*H];     // W1b
__device__ __half g_h_u2[H*H];    // W2@W1a
__device__ __half g_h_v2[H*H];    // W2@W1b
__device__ __half g_h_w2[H*H];    // W2

// ---------------- prep kernels ----------------

__global__ void comp_mat(const float* __restrict__ L, const float* __restrict__ R,
                         float* __restrict__ C) {
    __shared__ float lrow[H];
    int k = blockIdx.x, n = threadIdx.x;
    lrow[n] = L[k * H + n];
    __syncthreads();
    float acc = 0.f;
    for (int j = 0; j < H; j++) acc = fmaf(lrow[j], R[j * H + n], acc);
    C[k * H + n] = acc;
}

__global__ void comp_vec(const float* __restrict__ eu_w2, const float* __restrict__ eu_b2,
                         const float* __restrict__ ea_w1, const float* __restrict__ ea_b1,
                         const float* __restrict__ w1c, const float* __restrict__ eu_b1,
                         const float* __restrict__ w1a, const float* __restrict__ w1b,
                         const float* __restrict__ ew_w, const float* __restrict__ ew_b) {
    __shared__ float ra[H], rb[H], rw[H], rc[H], ru[H], rv[H];
    int n = blockIdx.x, k = threadIdx.x;
    float e2 = eu_b2[k];
    ra[k] = e2 * ea_w1[k * H + n];
    rb[k] = e2 * w1c[k * H + n];
    ru[k] = e2 * w1a[k * H + n];
    rv[k] = e2 * w1b[k * H + n];
    rw[k] = eu_w2[n * H + k] * ew_w[k];
    rc[k] = e2 * ew_w[k];
    __syncthreads();
    for (int s = 128; s > 0; s >>= 1) {
        if (k < s) {
            ra[k] += ra[k+s]; rb[k] += rb[k+s]; rw[k] += rw[k+s];
            rc[k] += rc[k+s]; ru[k] += ru[k+s]; rv[k] += rv[k+s];
        }
        __syncthreads();
    }
    if (k == 0) {
        g_cbsc[n] = ra[0] + ea_b1[n];
        g_cbth[n] = rb[0] + eu_b1[n];
        g_cU[n] = ru[0];
        g_cV[n] = rv[0];
        g_wcomp[n] = rw[0];
        if (n == 0) g_cconst[0] = rc[0] + ew_b[0];
    }
}

__global__ void conv_w(const float* __restrict__ W, __half* __restrict__ out) {
    int idx = blockIdx.x * 256 + threadIdx.x;
    int n = idx >> 8, k = idx & 255;
    out[(size_t)n * H + k] = __float2half_rn(W[(size_t)k * H + n]);
}

__global__ void deg_kernel(const int* __restrict__ deg, const int* __restrict__ batch,
                           const int* __restrict__ heads, const int* __restrict__ tails) {
    int n = blockIdx.x * 256 + threadIdx.x;
    int d = deg[n];
    float inv = 1.f / (1.f + (float)d);
    g_inv[n] = inv;
    g_rs[n] = (d > 0) ? inv : 0.f;
    int b = batch[n];
    g_ish[n] = (heads[b] == n) ? 1.f : 0.f;
    g_ist[n] = (tails[b] == n) ? 1.f : 0.f;
}

__global__ void init_be_kernel(const float* __restrict__ ef, const float* __restrict__ gall) {
    int t = blockIdx.x * 256 + threadIdx.x;
    int e = t >> 5, j = t & 31;
    const float* srcp = (j < 24) ? (ef + (size_t)e * 192 + j * 8) : (gall + (j - 24) * 8);
    float4 a = *(const float4*)srcp;
    float4 b = *(const float4*)(srcp + 4);
    __half2 h0 = __floats2half2_rn(a.x, a.y), h1 = __floats2half2_rn(a.z, a.w);
    __half2 h2 = __floats2half2_rn(b.x, b.y), h3 = __floats2half2_rn(b.z, b.w);
    uint4 u = make_uint4(*(uint32_t*)&h0, *(uint32_t*)&h1, *(uint32_t*)&h2, *(uint32_t*)&h3);
    *(uint4*)(g_be + (size_t)e * H + j * 8) = u;
}

__global__ void init_iter_kernel(float* __restrict__ dst) {
    int t = blockIdx.x * 256 + threadIdx.x;
    if (t < NN * H) dst[t] = 0.f;
    if (t < NN) g_s[t] = 0.f;
}

// ---------------- common MMA helpers ----------------

#define MMA_F16(d, a, b0, b1)                                               \
    asm volatile("mma.sync.aligned.m16n8k16.row.col.f32.f16.f16.f32 "       \
        "{%0,%1,%2,%3}, {%4,%5,%6,%7}, {%8,%9}, {%0,%1,%2,%3};"             \
        : "+f"((d)[0]), "+f"((d)[1]), "+f"((d)[2]), "+f"((d)[3])            \
        : "r"((a)[0]), "r"((a)[1]), "r"((a)[2]), "r"((a)[3]),               \
          "r"(b0), "r"(b1))

__device__ __forceinline__ uint32_t pack_h2(float x, float y) {
    __half2 h = __floats2half2_rn(x, y);
    return *(uint32_t*)&h;
}

// ---------------- fused edge GEMM: score(+softmax+scatter) | hidden-pre ----------------
// grid = 8192: blocks [0,4096) -> score half, [4096,8192) -> pre half
// score: ex = exp(sigmoid(relu(A@Bsc+bsc)@wv+wb)); s[recv]+=ex; agg[recv]+=ex*A
// pre  : g_pre = A@Bth + bth   (fp16, pre-activation; U/V/relu applied later)

#define AFSTRIDE 264
#define S_OFF_A    0                    // 64*264*2 = 33792
#define S_OFF_B    33792                // 256*40*2 = 20480
#define S_OFF_SB1  54272
#define S_OFF_SWV  55296
#define S_OFF_RSUM 56320
#define S_OFF_SEX  56576
#define S_OFF_RCV  56832
#define S_SMEM     57088
#define BSTRIDE 40

__global__ __launch_bounds__(256, 2) void edge_gemm(
    const __half* __restrict__ A,
    const __half* __restrict__ Bsc, const __half* __restrict__ Bth,
    const float* __restrict__ bsc, const float* __restrict__ bth,
    const float* __restrict__ wvp, const float* __restrict__ wbp,
    const int* __restrict__ recvp, float* __restrict__ aggdst)
{
    extern __shared__ char smem[];
    __half* Af = (__half*)(smem + S_OFF_A);
    __half* Bh = (__half*)(smem + S_OFF_B);
    float* sb1  = (float*)(smem + S_OFF_SB1);
    float* swv  = (float*)(smem + S_OFF_SWV);
    float* rsum = (float*)(smem + S_OFF_RSUM);
    float* sex  = (float*)(smem + S_OFF_SEX);
    int*   srcv = (int*)(smem + S_OFF_RCV);

    const int tid = threadIdx.x, lane = tid & 31, wid = tid >> 5;
    const int half = blockIdx.x >> 12;          // 0 = score, 1 = pre
    const int row0 = (blockIdx.x & 4095) * 64;
    const int mbase = (wid >> 2) * 32, nbase = (wid & 3) * 64;
    const __half* Bg = half ? Bth : Bsc;

    sb1[tid] = half ? bth[tid] : bsc[tid];
    if (!half) {
        swv[tid] = wvp[tid];
        if (tid < 64) { rsum[tid] = 0.f; srcv[tid] = recvp[row0 + tid]; }
    }

    // load full A tile (64 x 256 halves)
    {
        int r = tid >> 2, c0 = (tid & 3) * 64;
        #pragma unroll
        for (int j = 0; j < 8; j++) {
            uint4 u = *(const uint4*)(A + (size_t)(row0 + r) * H + c0 + j * 8);
            *(uint4*)&Af[r * AFSTRIDE + c0 + j * 8] = u;
        }
    }

    float acc[2][8][4];
    #pragma unroll
    for (int mf = 0; mf < 2; mf++)
        #pragma unroll
        for (int nf = 0; nf < 8; nf++)
            #pragma unroll
            for (int q = 0; q < 4; q++) acc[mf][nf][q] = 0.f;

    // B prefetch pipeline (row tid, 32-k chunks)
    const __half* bptr = Bg + (size_t)tid * H;
    uint4 bf[4];
    #pragma unroll
    for (int j = 0; j < 4; j++) bf[j] = *(const uint4*)(bptr + j * 8);

    for (int kt = 0; kt < H; kt += 32) {
        #pragma unroll
        for (int j = 0; j < 4; j++) *(uint4*)&Bh[tid * BSTRIDE + j * 8] = bf[j];
        __syncthreads();
        if (kt + 32 < H) {
            #pragma unroll
            for (int j = 0; j < 4; j++) bf[j] = *(const uint4*)(bptr + kt + 32 + j * 8);
        }
        #pragma unroll
        for (int ks = 0; ks < 2; ks++) {
            const int k0 = kt + ks * 16 + (lane & 3) * 2;
            uint32_t af[2][4];
            #pragma unroll
            for (int mf = 0; mf < 2; mf++) {
                int r = mbase + mf * 16 + (lane >> 2);
                af[mf][0] = *(uint32_t*)&Af[r * AFSTRIDE + k0];
                af[mf][1] = *(uint32_t*)&Af[(r + 8) * AFSTRIDE + k0];
                af[mf][2] = *(uint32_t*)&Af[r * AFSTRIDE + k0 + 8];
                af[mf][3] = *(uint32_t*)&Af[(r + 8) * AFSTRIDE + k0 + 8];
            }
            const int kb0 = ks * 16 + (lane & 3) * 2;
            #pragma unroll
            for (int nf = 0; nf < 8; nf++) {
                int n = nbase + nf * 8 + (lane >> 2);
                uint32_t b0 = *(uint32_t*)&Bh[n * BSTRIDE + kb0];
                uint32_t b1 = *(uint32_t*)&Bh[n * BSTRIDE + kb0 + 8];
                #pragma unroll
                for (int mf = 0; mf < 2; mf++)
                    MMA_F16(acc[mf][nf], af[mf], b0, b1);
            }
        }
        __syncthreads();
    }

    if (half) {
        // pre epilogue: store acc + bias as fp16
        #pragma unroll
        for (int mf = 0; mf < 2; mf++)
            #pragma unroll
            for (int nf = 0; nf < 8; nf++) {
                int rA = mbase + mf * 16 + (lane >> 2);
                int rB = rA + 8;
                int c0 = nbase + nf * 8 + (lane & 3) * 2;
                float bb0 = sb1[c0], bb1 = sb1[c0 + 1];
                *(uint32_t*)(g_pre + (size_t)(row0 + rA) * H + c0) =
                    pack_h2(acc[mf][nf][0] + bb0, acc[mf][nf][1] + bb1);
                *(uint32_t*)(g_pre + (size_t)(row0 + rB) * H + c0) =
                    pack_h2(acc[mf][nf][2] + bb0, acc[mf][nf][3] + bb1);
            }
    } else {
        // score epilogue
        float part[2][2] = {{0.f, 0.f}, {0.f, 0.f}};
        #pragma unroll
        for (int mf = 0; mf < 2; mf++)
            #pragma unroll
            for (int nf = 0; nf < 8; nf++) {
                int c0 = nbase + nf * 8 + (lane & 3) * 2;
                float w0 = swv[c0], w1 = swv[c0 + 1];
                float bb0 = sb1[c0], bb1 = sb1[c0 + 1];
                float v0 = fmaxf(acc[mf][nf][0] + bb0, 0.f);
                float v1 = fmaxf(acc[mf][nf][1] + bb1, 0.f);
                float v2 = fmaxf(acc[mf][nf][2] + bb0, 0.f);
                float v3 = fmaxf(acc[mf][nf][3] + bb1, 0.f);
                part[mf][0] = fmaf(v0, w0, fmaf(v1, w1, part[mf][0]));
                part[mf][1] = fmaf(v2, w0, fmaf(v3, w1, part[mf][1]));
            }
        #pragma unroll
        for (int off = 1; off <= 2; off <<= 1)
            #pragma unroll
            for (int mf = 0; mf < 2; mf++) {
                part[mf][0] += __shfl_xor_sync(0xffffffffu, part[mf][0], off);
                part[mf][1] += __shfl_xor_sync(0xffffffffu, part[mf][1], off);
            }
        if ((lane & 3) == 0) {
            #pragma unroll
            for (int mf = 0; mf < 2; mf++) {
                atomicAdd(&rsum[mbase + mf * 16 + (lane >> 2)],     part[mf][0]);
                atomicAdd(&rsum[mbase + mf * 16 + (lane >> 2) + 8], part[mf][1]);
            }
        }
        __syncthreads();
        if (tid < 64) {
            float sg = 1.f / (1.f + expf(-(rsum[tid] + wbp[0])));
            float ex = expf(sg);
            sex[tid] = ex;
            atomicAdd(&g_s[srcv[tid]], ex);
        }
        __syncthreads();
        // scatter ex*A from smem (unnormalized)
        int r = tid >> 2, c0 = (tid & 3) * 64;
        float exv = sex[r];
        float* drow = aggdst + (size_t)srcv[r] * H + c0;
        const __half* arow = Af + r * AFSTRIDE + c0;
        #pragma unroll
        for (int j = 0; j < 16; j++) {
            float2 f0 = __half22float2(*(const __half2*)(arow + j * 4));
            float2 f1 = __half22float2(*(const __half2*)(arow + j * 4 + 2));
            asm volatile("red.global.add.v4.f32 [%0], {%1, %2, %3, %4};"
                         :: "l"(drow + j * 4), "f"(exv * f0.x), "f"(exv * f0.y),
                            "f"(exv * f1.x), "f"(exv * f1.y) : "memory");
        }
    }
}

// ---------------- node GEMM: roles U | V | bv from row-scaled agg ----------------
// role 0: g_U  = agg'@Bu + rs*cU + ish*fhU + ist*ftU
// role 1: g_V  = agg'@Bv + rs*cV + ish*fhV + ist*ftV
// role 2: g_bv = agg'@Bw2 + rs*b2           (last iter only)
// agg' = agg * (s>0 ? inv/s : 0) row-scaled

#define N_OFF_AH 0
#define N_OFF_BH 5120
#define N_OFF_CV 25600
#define N_OFF_FH 26624
#define N_OFF_FT 27648
#define N_OFF_R1 28672
#define N_OFF_R2 28928
#define N_OFF_I1 29184
#define N_OFF_I2 29440
#define N_SMEM   29696
#define ASTRIDE 40

__global__ __launch_bounds__(256) void node_gemm(
    const __half* __restrict__ Bu, const __half* __restrict__ Bv,
    const __half* __restrict__ Bw2,
    const float* __restrict__ cU, const float* __restrict__ cV,
    const float* __restrict__ cBv,
    const float* __restrict__ fhU, const float* __restrict__ ftU,
    const float* __restrict__ fhV, const float* __restrict__ ftV)
{
    extern __shared__ char smem[];
    __half* Ah = (__half*)(smem + N_OFF_AH);
    __half* Bh = (__half*)(smem + N_OFF_BH);
    float* scv = (float*)(smem + N_OFF_CV);
    float* sfh = (float*)(smem + N_OFF_FH);
    float* sft = (float*)(smem + N_OFF_FT);
    float* s_r1 = (float*)(smem + N_OFF_R1);
    float* s_r2 = (float*)(smem + N_OFF_R2);
    float* s_i1 = (float*)(smem + N_OFF_I1);
    float* s_i2 = (float*)(smem + N_OFF_I2);

    const int tid = threadIdx.x, lane = tid & 31, wid = tid >> 5;
    const int role = blockIdx.x >> 8;
    const int row0 = (blockIdx.x & 255) * 64;
    const int mbase = (wid >> 2) * 32, nbase = (wid & 3) * 64;

    const __half* Bg = (role == 0) ? Bu : (role == 1) ? Bv : Bw2;
    const float* cvec = (role == 0) ? cU : (role == 1) ? cV : cBv;
    const float* fh = (role == 0) ? fhU : (role == 1) ? fhV : nullptr;
    const float* ft = (role == 0) ? ftU : (role == 1) ? ftV : nullptr;
    float* outp = (role == 0) ? g_U : (role == 1) ? g_V : g_bv;

    scv[tid] = cvec ? cvec[tid] : 0.f;
    sfh[tid] = fh ? fh[tid] : 0.f;
    sft[tid] = ft ? ft[tid] : 0.f;
    if (tid < 64) {
        int n = row0 + tid;
        float s = g_s[n];
        s_r1[tid] = (s > 0.f) ? g_inv[n] / s : 0.f;
        s_r2[tid] = g_rs[n];
        s_i1[tid] = g_ish[n];
        s_i2[tid] = g_ist[n];
    }
    __syncthreads();

    float acc[2][8][4];
    #pragma unroll
    for (int mf = 0; mf < 2; mf++)
        #pragma unroll
        for (int nf = 0; nf < 8; nf++)
            #pragma unroll
            for (int q = 0; q < 4; q++) acc[mf][nf][q] = 0.f;

    const int arow = tid >> 2, ac0 = (tid & 3) * 8;

    for (int kt = 0; kt < H; kt += 32) {
        {
            float x[8];
            *(float4*)&x[0] = *(const float4*)(g_agg + (size_t)(row0 + arow) * H + kt + ac0);
            *(float4*)&x[4] = *(const float4*)(g_agg + (size_t)(row0 + arow) * H + kt + ac0 + 4);
            float sc = s_r1[arow];
            uint4 u;
            u.x = pack_h2(x[0] * sc, x[1] * sc);
            u.y = pack_h2(x[2] * sc, x[3] * sc);
            u.z = pack_h2(x[4] * sc, x[5] * sc);
            u.w = pack_h2(x[6] * sc, x[7] * sc);
            *(uint4*)&Ah[arow * ASTRIDE + ac0] = u;
        }
        {
            const __half* bsrc = Bg + (size_t)tid * H + kt;
            #pragma unroll
            for (int j = 0; j < 4; j++)
                *(uint4*)&Bh[tid * BSTRIDE + j * 8] = *(const uint4*)(bsrc + j * 8);
        }
        __syncthreads();
        #pragma unroll
        for (int ks = 0; ks < 2; ks++) {
            const int k0 = ks * 16 + (lane & 3) * 2;
            uint32_t af[2][4];
            #pragma unroll
            for (int mf = 0; mf < 2; mf++) {
                int r = mbase + mf * 16 + (lane >> 2);
                af[mf][0] = *(uint32_t*)&Ah[r * ASTRIDE + k0];
                af[mf][1] = *(uint32_t*)&Ah[(r + 8) * ASTRIDE + k0];
                af[mf][2] = *(uint32_t*)&Ah[r * ASTRIDE + k0 + 8];
                af[mf][3] = *(uint32_t*)&Ah[(r + 8) * ASTRIDE + k0 + 8];
            }
            #pragma unroll
            for (int nf = 0; nf < 8; nf++) {
                int n = nbase + nf * 8 + (lane >> 2);
                uint32_t b0 = *(uint32_t*)&Bh[n * BSTRIDE + k0];
                uint32_t b1 = *(uint32_t*)&Bh[n * BSTRIDE + k0 + 8];
                #pragma unroll
                for (int mf = 0; mf < 2; mf++)
                    MMA_F16(acc[mf][nf], af[mf], b0, b1);
            }
        }
        __syncthreads();
    }

    #pragma unroll
    for (int mf = 0; mf < 2; mf++)
        #pragma unroll
        for (int nf = 0; nf < 8; nf++) {
            int rA = mbase + mf * 16 + (lane >> 2);
            int rB = rA + 8;
            int c0 = nbase + nf * 8 + (lane & 3) * 2;
            float cv0 = scv[c0], cv1 = scv[c0 + 1];
            float fh0 = sfh[c0], fh1 = sfh[c0 + 1];
            float ft0 = sft[c0], ft1 = sft[c0 + 1];
            float2 v0, v1;
            v0.x = acc[mf][nf][0] + s_r2[rA] * cv0 + s_i1[rA] * fh0 + s_i2[rA] * ft0;
            v0.y = acc[mf][nf][1] + s_r2[rA] * cv1 + s_i1[rA] * fh1 + s_i2[rA] * ft1;
            v1.x = acc[mf][nf][2] + s_r2[rB] * cv0 + s_i1[rB] * fh0 + s_i2[rB] * ft0;
            v1.y = acc[mf][nf][3] + s_r2[rB] * cv1 + s_i1[rB] * fh1 + s_i2[rB] * ft1;
            *(float2*)(outp + (size_t)(row0 + rA) * H + c0) = v0;
            *(float2*)(outp + (size_t)(row0 + rB) * H + c0) = v1;
        }
}

// ---------------- finalize: hidden = relu(pre + U[src] + V[recv]) ----------------

__global__ void finalize_hidden(const int* __restrict__ srcp, const int* __restrict__ recvp) {
    int t = blockIdx.x * 256 + threadIdx.x;      // E*32 threads, 8 cols each
    int e = t >> 5, j = (t & 31) * 8;
    int s = srcp[e], r = recvp[e];
    uint4 ph = *(const uint4*)(g_pre + (size_t)e * H + j);
    float4 u0 = *(const float4*)(g_U + (size_t)s * H + j);
    float4 u1 = *(const float4*)(g_U + (size_t)s * H + j + 4);
    float4 v0 = *(const float4*)(g_V + (size_t)r * H + j);
    float4 v1 = *(const float4*)(g_V + (size_t)r * H + j + 4);
    float2 p0 = __half22float2(*(__half2*)&ph.x);
    float2 p1 = __half22float2(*(__half2*)&ph.y);
    float2 p2 = __half22float2(*(__half2*)&ph.z);
    float2 p3 = __half22float2(*(__half2*)&ph.w);
    uint4 o;
    o.x = pack_h2(fmaxf(p0.x + u0.x + v0.x, 0.f), fmaxf(p0.y + u0.y + v0.y, 0.f));
    o.y = pack_h2(fmaxf(p1.x + u0.z + v0.z, 0.f), fmaxf(p1.y + u0.w + v0.w, 0.f));
    o.z = pack_h2(fmaxf(p2.x + u1.x + v1.x, 0.f), fmaxf(p2.y + u1.y + v1.y, 0.f));
    o.w = pack_h2(fmaxf(p3.x + u1.z + v1.z, 0.f), fmaxf(p3.y + u1.w + v1.w, 0.f));
    *(uint4*)(g_hidden + (size_t)e * H + j) = o;
}

// last iter: w_e = sigmoid(relu(pre + U[src] + V[recv]) @ wcomp + cconst)
__global__ void finalize_we(const int* __restrict__ srcp, const int* __restrict__ recvp,
                            float* __restrict__ out) {
    __shared__ float wc[H];
    int tid = threadIdx.x, lane = tid & 31, wid = tid >> 5;
    wc[tid] = g_wcomp[tid];
    __syncthreads();
    int e = blockIdx.x * 8 + wid;
    int s = srcp[e], r = recvp[e];
    int j = lane * 8;
    uint4 ph = *(const uint4*)(g_pre + (size_t)e * H + j);
    float4 u0 = *(const float4*)(g_U + (size_t)s * H + j);
    float4 u1 = *(const float4*)(g_U + (size_t)s * H + j + 4);
    float4 v0 = *(const float4*)(g_V + (size_t)r * H + j);
    float4 v1 = *(const float4*)(g_V + (size_t)r * H + j + 4);
    float2 p0 = __half22float2(*(__half2*)&ph.x);
    float2 p1 = __half22float2(*(__half2*)&ph.y);
    float2 p2 = __half22float2(*(__half2*)&ph.z);
    float2 p3 = __half22float2(*(__half2*)&ph.w);
    const float* w = wc + j;
    float acc = fmaxf(p0.x + u0.x + v0.x, 0.f) * w[0]
              + fmaxf(p0.y + u0.y + v0.y, 0.f) * w[1]
              + fmaxf(p1.x + u0.z + v0.z, 0.f) * w[2]
              + fmaxf(p1.y + u0.w + v0.w, 0.f) * w[3]
              + fmaxf(p2.x + u1.x + v1.x, 0.f) * w[4]
              + fmaxf(p2.y + u1.y + v1.y, 0.f) * w[5]
              + fmaxf(p3.x + u1.z + v1.z, 0.f) * w[6]
              + fmaxf(p3.y + u1.w + v1.w, 0.f) * w[7];
    #pragma unroll
    for (int off = 16; off > 0; off >>= 1) acc += __shfl_xor_sync(0xffffffffu, acc, off);
    if (lane == 0) out[e] = 1.f / (1.f + expf(-(acc + g_cconst[0])));
}

// ---------------- graph readout ----------------

__global__ void gmax_kernel(const int* __restrict__ heads, const int* __restrict__ tails) {
    int g = blockIdx.x, j = threadIdx.x;
    float mx = -3.4e38f;
    int base = g * 256;
    for (int n = 0; n < 256; n++)
        mx = fmaxf(mx, g_bv[(size_t)(base + n) * H + j]);
    g_gG[g * 768 + j]       = mx;
    g_gG[g * 768 + 256 + j] = g_bv[(size_t)heads[g] * H + j];
    g_gG[g * 768 + 512 + j] = g_bv[(size_t)tails[g] * H + j];
}

__global__ void gmlp_kernel(const float* __restrict__ W1, const float* __restrict__ b1,
                            const float* __restrict__ w2, const float* __restrict__ b2) {
    __shared__ float row[768];
    __shared__ float red[256];
    int g = blockIdx.x, tid = threadIdx.x;
    for (int i = tid; i < 768; i += 256) row[i] = g_gG[g * 768 + i];
    __syncthreads();
    float h = b1[tid];
    for (int k = 0; k < 768; k++) h = fmaf(row[k], W1[(size_t)k * 256 + tid], h);
    h = fmaxf(h, 0.f);
    red[tid] = h * w2[tid];
    __syncthreads();
    for (int s = 128; s > 0; s >>= 1) {
        if (tid < s) red[tid] += red[tid + s];
        __syncthreads();
    }
    if (tid == 0) g_z[g] = red[0] + b2[0];
}

__global__ void gout_kernel(float* __restrict__ out) {
    __shared__ float zs[NG];
    int tid = threadIdx.x;
    if (tid < NG) zs[tid] = g_z[tid];
    __syncthreads();
    float m = -3.4e38f;
    for (int g = 0; g < NG; g++) m = fmaxf(m, zs[g]);
    float denom = 0.f;
    for (int g = 0; g < NG; g++) denom += expf(zs[g] - m);
    float acc = 0.f;
    for (int g = 0; g < NG; g++) acc += (expf(zs[g] - m) / denom) * g_gG[g * 768 + tid];
    out[tid] = acc;
}

// ---------------- launch ----------------

static float* dev_ptr(const void* sym) { void* p = nullptr; cudaGetSymbolAddress(&p, sym); return (float*)p; }

extern "C" void kernel_launch(void* const* d_in, const int* in_sizes, int n_in,
                              void* d_out, int out_size) {
    const float* ef     = (const float*)d_in[0];
    const float* gall   = (const float*)d_in[1];
    const float* ea_w1  = (const float*)d_in[2];
    const float* ea_b1  = (const float*)d_in[3];
    const float* ea_w2  = (const float*)d_in[4];
    const float* ea_b2  = (const float*)d_in[5];
    const float* eu_w1  = (const float*)d_in[6];
    const float* eu_b1  = (const float*)d_in[7];
    const float* eu_w2  = (const float*)d_in[8];
    const float* eu_b2  = (const float*)d_in[9];
    const float* gw_w1  = (const float*)d_in[10];
    const float* gw_b1  = (const float*)d_in[11];
    const float* gw_w2  = (const float*)d_in[12];
    const float* gw_b2  = (const float*)d_in[13];
    const float* ew_w   = (const float*)d_in[14];
    const float* ew_b   = (const float*)d_in[15];
    const int*   eidx   = (const int*)d_in[16];
    const int*   deg    = (const int*)d_in[17];
    const int*   batch  = (const int*)d_in[18];
    const int*   heads  = (const int*)d_in[19];
    const int*   tails  = (const int*)d_in[20];
    const int* src  = eidx;
    const int* recv = eidx + E_TOT;
    float* out = (float*)d_out;
    const float* w1a = eu_w1;
    const float* w1b = eu_w1 + 258 * H;
    const float* w1c = eu_w1 + 516 * H;

    cudaFuncSetAttribute(edge_gemm, cudaFuncAttributeMaxDynamicSharedMemorySize, S_SMEM);
    cudaFuncSetAttribute(node_gemm, cudaFuncAttributeMaxDynamicSharedMemorySize, N_SMEM);

    float *p_Wsc = dev_ptr(g_Wsc), *p_Wth = dev_ptr(g_Wth);
    float *p_WU2 = dev_ptr(g_WU2), *p_WV2 = dev_ptr(g_WV2);
    float *p_cbsc = dev_ptr(g_cbsc), *p_cbth = dev_ptr(g_cbth);
    float *p_cU = dev_ptr(g_cU), *p_cV = dev_ptr(g_cV);
    __half *p_be = (__half*)dev_ptr(g_be), *p_hidden = (__half*)dev_ptr(g_hidden);
    float *p_agg = dev_ptr(g_agg);
    __half *h_sc0 = (__half*)dev_ptr(g_h_sc0), *h_sc = (__half*)dev_ptr(g_h_sc);
    __half *h_th0 = (__half*)dev_ptr(g_h_th0), *h_th = (__half*)dev_ptr(g_h_th);
    __half *h_u = (__half*)dev_ptr(g_h_u), *h_v = (__half*)dev_ptr(g_h_v);
    __half *h_u2 = (__half*)dev_ptr(g_h_u2), *h_v2 = (__half*)dev_ptr(g_h_v2);
    __half *h_w2 = (__half*)dev_ptr(g_h_w2);

    // ---- prep ----
    deg_kernel<<<NN / 256, 256>>>(deg, batch, heads, tails);
    comp_mat<<<256, 256>>>(eu_w2, ea_w1, p_Wsc);
    comp_mat<<<256, 256>>>(eu_w2, w1c, p_Wth);
    comp_mat<<<256, 256>>>(eu_w2, w1a, p_WU2);
    comp_mat<<<256, 256>>>(eu_w2, w1b, p_WV2);
    comp_vec<<<256, 256>>>(eu_w2, eu_b2, ea_w1, ea_b1, w1c, eu_b1, w1a, w1b, ew_w, ew_b);
    conv_w<<<256, 256>>>(ea_w1, h_sc0);
    conv_w<<<256, 256>>>(p_Wsc, h_sc);
    conv_w<<<256, 256>>>(w1c, h_th0);
    conv_w<<<256, 256>>>(p_Wth, h_th);
    conv_w<<<256, 256>>>(w1a, h_u);
    conv_w<<<256, 256>>>(w1b, h_v);
    conv_w<<<256, 256>>>(p_WU2, h_u2);
    conv_w<<<256, 256>>>(p_WV2, h_v2);
    conv_w<<<256, 256>>>(eu_w2, h_w2);
    init_be_kernel<<<E_TOT / 8, 256>>>(ef, gall);

    for (int it = 0; it < 3; it++) {
        const __half* Acur = (it == 0) ? p_be : p_hidden;

        init_iter_kernel<<<(NN * H + 255) / 256, 256>>>(p_agg);
        // fused score(+scatter) | hidden-pre
        edge_gemm<<<8192, 256, S_SMEM>>>(
            Acur,
            (it == 0) ? h_sc0 : h_sc, (it == 0) ? h_th0 : h_th,
            (it == 0) ? ea_b1 : p_cbsc, (it == 0) ? eu_b1 : p_cbth,
            ea_w2, ea_b2, recv, p_agg);
        // U | V (| bv on last iter) straight from scaled agg
        node_gemm<<<(it == 2) ? 768 : 512, 256, N_SMEM>>>(
            (it == 0) ? h_u : h_u2, (it == 0) ? h_v : h_v2, h_w2,
            (it == 0) ? nullptr : p_cU, (it == 0) ? nullptr : p_cV, eu_b2,
            eu_w1 + 256 * H, eu_w1 + 257 * H, eu_w1 + 514 * H, eu_w1 + 515 * H);
        // finalize hidden / fused w_e
        if (it < 2)
            finalize_hidden<<<E_TOT / 8, 256>>>(src, recv);
        else
            finalize_we<<<E_TOT / 8, 256>>>(src, recv, out);
    }

    gmax_kernel<<<NG, 256>>>(heads, tails);
    gmlp_kernel<<<NG, 256>>>(gw_w1, gw_b1, gw_w2, gw_b2);
    gout_kernel<<<1, 768>>>(out + E_TOT);
}